// round 9
// baseline (speedup 1.0000x reference)
#include <cuda_runtime.h>
#include <math.h>
#include <stdint.h>

// ---------------------------------------------------------------------------
// Problem constants
// ---------------------------------------------------------------------------
#define Bq      8
#define NFULL   4096
#define NLAT    1024
#define CDIM    256
#define HEADS   8
#define VDIM    32
#define MBIG    (Bq*NFULL)   // 32768
#define MLAT    (Bq*NLAT)    // 8192

// ---------------------------------------------------------------------------
// Scratch (device globals; no allocation allowed)
// ---------------------------------------------------------------------------
__device__ float g_big0[MBIG*CDIM];   // h0 / up-attn output
__device__ float g_big1[MBIG*CDIM];   // down value / de_fc1 output
__device__ float g_lat [MLAT*CDIM];   // latent h
__device__ float g_pa  [MLAT*CDIM];   // pos_att output (latent blocks)
__device__ float g_t1  [MLAT*CDIM];   // value (latent) / fc1 output
__device__ float g_t3  [MLAT*CDIM];   // residual branch
__device__ float g_wcat[CDIM*CDIM];   // repacked per-head attention value weight
__device__ float g_smin[HEADS*NFULL]; // per-(h,row) sd min
__device__ float g_sinv[HEADS*NFULL]; // per-(h,row) 1/denominator
__device__ float g_sthr[HEADS*NFULL]; // per-(h,row) threshold (inf for global)

// ---------------------------------------------------------------------------
// Helpers
// ---------------------------------------------------------------------------
__device__ __forceinline__ float gelu_f(float v){
    // JAX default gelu (approximate=True): 0.5*x*(1+tanh(sqrt(2/pi)*(x+0.044715 x^3)))
    float t = tanhf(0.7978845608028654f * (v + 0.044715f * v * v * v));
    return 0.5f * v * (1.0f + t);
}

__device__ __forceinline__ float scale_from_r(float r){
    // 0.25*pi*(1-1e-7) computed in f64, rounded to f32 (matches JAX weak-typing)
    const float A = 0.7853980848576320f;
    return tanf(A * (1.0f + sinf(r)));
}

// ---------------------------------------------------------------------------
// Encoder: out = gelu(x @ W[4,256] + b), one block per row
// ---------------------------------------------------------------------------
__global__ void encoder_kernel(const float* __restrict__ x,
                               const float* __restrict__ W,
                               const float* __restrict__ bias,
                               float* __restrict__ out){
    int m = blockIdx.x;
    int c = threadIdx.x;
    const float* xr = x + (size_t)m * 4;
    float v = bias[c];
    v += xr[0]*W[c] + xr[1]*W[256+c] + xr[2]*W[512+c] + xr[3]*W[768+c];
    out[(size_t)m*256 + c] = gelu_f(v);
}

// ---------------------------------------------------------------------------
// Repack per-head value weight [H,C,VD] -> [C, H*VD] (col = h*32+k)
// ---------------------------------------------------------------------------
__global__ void repack_w_kernel(const float* __restrict__ w, float* __restrict__ wcat){
    int idx = blockIdx.x * 256 + threadIdx.x;   // 65536 total
    int j = idx >> 8;
    int c = idx & 255;
    int h = c >> 5;
    int k = c & 31;
    wcat[idx] = w[h*(CDIM*VDIM) + j*VDIM + k];
}

// ---------------------------------------------------------------------------
// Generic GEMM: out[M,256] = epi(A[M,256] @ W[256,256] [+bias] [+addin]) [gelu]
// 64x256 tile per block, 8x8 microtile per thread, K tiles of 32.
// ---------------------------------------------------------------------------
template<bool BIAS, bool GELU, bool ADDIN>
__global__ __launch_bounds__(256)
void gemm256_kernel(const float* __restrict__ A, const float* __restrict__ W,
                    const float* __restrict__ bias, const float* __restrict__ addin,
                    float* __restrict__ out){
    __shared__ float As[64][36];
    __shared__ float Ws[32][256];
    int tid = threadIdx.x;
    int j0  = blockIdx.x * 64;
    int jb  = tid >> 5;       // 0..7 (row octet)
    int cb  = tid & 31;       // 0..31 (col octet)

    float acc[8][8];
    #pragma unroll
    for (int u=0;u<8;u++)
        #pragma unroll
        for (int v=0;v<8;v++) acc[u][v]=0.f;

    for (int k0 = 0; k0 < 256; k0 += 32){
        #pragma unroll
        for (int i=0;i<2;i++){
            int id = tid + 256*i;
            int j = id >> 3, q = id & 7;
            float4 a4 = *reinterpret_cast<const float4*>(A + (size_t)(j0+j)*256 + k0 + q*4);
            As[j][q*4+0]=a4.x; As[j][q*4+1]=a4.y; As[j][q*4+2]=a4.z; As[j][q*4+3]=a4.w;
        }
        #pragma unroll
        for (int i=0;i<8;i++){
            int id = tid + 256*i;
            int kk = id >> 6, f = id & 63;
            float4 w4 = *reinterpret_cast<const float4*>(W + (size_t)(k0+kk)*256 + f*4);
            *reinterpret_cast<float4*>(&Ws[kk][f*4]) = w4;
        }
        __syncthreads();
        #pragma unroll
        for (int kk=0; kk<32; kk++){
            float a[8], w[8];
            #pragma unroll
            for (int u=0;u<8;u++) a[u] = As[jb*8+u][kk];   // warp-broadcast
            float4 w0 = *reinterpret_cast<const float4*>(&Ws[kk][cb*8]);
            float4 w1 = *reinterpret_cast<const float4*>(&Ws[kk][cb*8+4]);
            w[0]=w0.x; w[1]=w0.y; w[2]=w0.z; w[3]=w0.w;
            w[4]=w1.x; w[5]=w1.y; w[6]=w1.z; w[7]=w1.w;
            #pragma unroll
            for (int u=0;u<8;u++)
                #pragma unroll
                for (int v=0;v<8;v++) acc[u][v] += a[u]*w[v];
        }
        __syncthreads();
    }

    float br[8];
    if (BIAS){
        #pragma unroll
        for (int v=0;v<8;v++) br[v] = bias[cb*8+v];
    }
    #pragma unroll
    for (int u=0;u<8;u++){
        size_t base = (size_t)(j0 + jb*8 + u)*256 + cb*8;
        float vals[8];
        #pragma unroll
        for (int v=0;v<8;v++){
            float t = acc[u][v];
            if (BIAS)  t += br[v];
            if (ADDIN) t += addin[base+v];
            if (GELU)  t = gelu_f(t);
            vals[v]=t;
        }
        *reinterpret_cast<float4*>(out+base)   = make_float4(vals[0],vals[1],vals[2],vals[3]);
        *reinterpret_cast<float4*>(out+base+4) = make_float4(vals[4],vals[5],vals[6],vals[7]);
    }
}

// ---------------------------------------------------------------------------
// Softmax stats (global, no mask): per row min(sd) and 1/sum(exp(min-sd)); thr=inf
// One block (256 thr) per (h,row); row data cached in dynamic smem.
// ---------------------------------------------------------------------------
__global__ void stats_global_kernel(const float* __restrict__ m,
                                    const float* __restrict__ r,
                                    float* __restrict__ sdmin, float* __restrict__ invden,
                                    float* __restrict__ thr, int Nq, int Nk){
    extern __shared__ float sbuf[];
    __shared__ float red[256];
    int row = blockIdx.x;
    int h = row / Nq;
    float scale = scale_from_r(r[h]);
    const float* mr = m + (size_t)row * Nk;
    float lmin = 3.402823466e38f;
    for (int i = threadIdx.x; i < Nk; i += 256){
        float sd = mr[i] * scale;
        sbuf[i] = sd;
        lmin = fminf(lmin, sd);
    }
    red[threadIdx.x] = lmin;
    __syncthreads();
    for (int s=128; s>0; s>>=1){
        if (threadIdx.x < s) red[threadIdx.x] = fminf(red[threadIdx.x], red[threadIdx.x+s]);
        __syncthreads();
    }
    float mn = red[0];
    __syncthreads();
    float ls = 0.f;
    for (int i = threadIdx.x; i < Nk; i += 256) ls += __expf(mn - sbuf[i]);
    red[threadIdx.x] = ls;
    __syncthreads();
    for (int s=128; s>0; s>>=1){
        if (threadIdx.x < s) red[threadIdx.x] += red[threadIdx.x+s];
        __syncthreads();
    }
    if (threadIdx.x == 0){
        sdmin[row]  = mn;
        invden[row] = 1.0f / red[0];
        thr[row]    = __int_as_float(0x7f800000);  // +inf
    }
}

// ---------------------------------------------------------------------------
// Softmax stats (local, 30th percentile mask), Nk=1024 fixed.
// Bitonic sort in smem, linear-interp percentile, masked denom.
// ---------------------------------------------------------------------------
__global__ void stats_local_kernel(const float* __restrict__ m,
                                   const float* __restrict__ r,
                                   float* __restrict__ sdmin, float* __restrict__ invden,
                                   float* __restrict__ thr, int Nq){
    __shared__ float s[1024];
    __shared__ float red[256];
    int row = blockIdx.x;
    int h = row / Nq;
    float scale = scale_from_r(r[h]);
    const float* mr = m + (size_t)row * 1024;
    for (int i = threadIdx.x; i < 1024; i += 256) s[i] = mr[i] * scale;
    __syncthreads();
    // bitonic sort ascending
    for (int k = 2; k <= 1024; k <<= 1){
        for (int j = k >> 1; j > 0; j >>= 1){
            for (int i = threadIdx.x; i < 1024; i += 256){
                int ixj = i ^ j;
                if (ixj > i){
                    bool up = ((i & k) == 0);
                    float a = s[i], b = s[ixj];
                    if ((a > b) == up){ s[i] = b; s[ixj] = a; }
                }
            }
            __syncthreads();
        }
    }
    float pos = 1023.0f * (30.0f / 100.0f);   // 306.9
    int lo = (int)pos;
    float fr = pos - (float)lo;
    float th = s[lo] + fr * (s[lo+1] - s[lo]);
    float mn = s[0];
    float ls = 0.f;
    for (int i = threadIdx.x; i < 1024; i += 256){
        float v = s[i];
        if (v <= th) ls += __expf(mn - v);
    }
    red[threadIdx.x] = ls;
    __syncthreads();
    for (int st=128; st>0; st>>=1){
        if (threadIdx.x < st) red[threadIdx.x] += red[threadIdx.x+st];
        __syncthreads();
    }
    if (threadIdx.x == 0){
        sdmin[row]  = mn;
        invden[row] = 1.0f / red[0];
        thr[row]    = th;
    }
}

// ---------------------------------------------------------------------------
// Attention apply: out[b, j, h*32+k] = gelu( sum_n p[h,j,n] * V[b,n,h*32+k] )
// p computed on the fly from m_dist + stats. Block = (64 j-rows) x (head).
// Output columns = 256 = (b,k) pairs. Same 8x8 microkernel as gemm256.
// ---------------------------------------------------------------------------
__global__ __launch_bounds__(256)
void attn_apply_kernel(const float* __restrict__ m_dist,  // [H,Nq,Nk]
                       const float* __restrict__ r,       // [H]
                       const float* __restrict__ sdmin,
                       const float* __restrict__ invden,
                       const float* __restrict__ thr,
                       const float* __restrict__ V,       // [B, Nk, 256]
                       float* __restrict__ out,           // [B, Nq, 256]
                       int Nq, int Nk){
    __shared__ float Ps[64][36];     // [j][nn]
    __shared__ float Vs[32][256];    // [nn][c], c = b*32+k
    __shared__ float s_min[64], s_inv[64], s_thr[64];
    int tid = threadIdx.x;
    int h  = blockIdx.y;
    int j0 = blockIdx.x * 64;
    float scale = scale_from_r(r[h]);
    if (tid < 64){
        int row = h*Nq + j0 + tid;
        s_min[tid] = sdmin[row];
        s_inv[tid] = invden[row];
        s_thr[tid] = thr[row];
    }
    __syncthreads();
    int jb = tid >> 5;
    int cb = tid & 31;
    int b  = cb >> 2;             // (cb*8)/32
    int kbase = (cb & 3) * 8;

    float acc[8][8];
    #pragma unroll
    for (int u=0;u<8;u++)
        #pragma unroll
        for (int v=0;v<8;v++) acc[u][v]=0.f;

    const float* mbase = m_dist + ((size_t)h*Nq + j0) * Nk;

    for (int n0 = 0; n0 < Nk; n0 += 32){
        // fill P (weights): 64x32, 2 float4 per thread
        #pragma unroll
        for (int i=0;i<2;i++){
            int id = tid + 256*i;
            int j = id >> 3, q = id & 7;
            float4 m4 = *reinterpret_cast<const float4*>(mbase + (size_t)j*Nk + n0 + q*4);
            float mn = s_min[j], iv = s_inv[j], th = s_thr[j];
            float sd0 = m4.x*scale, sd1 = m4.y*scale, sd2 = m4.z*scale, sd3 = m4.w*scale;
            Ps[j][q*4+0] = (sd0 <= th) ? __expf(mn - sd0)*iv : 0.f;
            Ps[j][q*4+1] = (sd1 <= th) ? __expf(mn - sd1)*iv : 0.f;
            Ps[j][q*4+2] = (sd2 <= th) ? __expf(mn - sd2)*iv : 0.f;
            Ps[j][q*4+3] = (sd3 <= th) ? __expf(mn - sd3)*iv : 0.f;
        }
        // fill V tile: 32 x 256 floats
        #pragma unroll
        for (int i=0;i<8;i++){
            int id = tid + 256*i;
            int nn = id >> 6, f = id & 63;
            int bb = f >> 3, kq = f & 7;
            float4 v4 = *reinterpret_cast<const float4*>(
                V + ((size_t)bb*Nk + n0 + nn)*256 + h*32 + kq*4);
            *reinterpret_cast<float4*>(&Vs[nn][bb*32 + kq*4]) = v4;
        }
        __syncthreads();
        #pragma unroll
        for (int nn=0; nn<32; nn++){
            float p[8], w[8];
            #pragma unroll
            for (int u=0;u<8;u++) p[u] = Ps[jb*8+u][nn];   // warp-broadcast
            float4 v0 = *reinterpret_cast<const float4*>(&Vs[nn][cb*8]);
            float4 v1 = *reinterpret_cast<const float4*>(&Vs[nn][cb*8+4]);
            w[0]=v0.x; w[1]=v0.y; w[2]=v0.z; w[3]=v0.w;
            w[4]=v1.x; w[5]=v1.y; w[6]=v1.z; w[7]=v1.w;
            #pragma unroll
            for (int u=0;u<8;u++)
                #pragma unroll
                for (int v=0;v<8;v++) acc[u][v] += p[u]*w[v];
        }
        __syncthreads();
    }

    // epilogue: gelu, scatter to [B, Nq, 256]
    #pragma unroll
    for (int u=0;u<8;u++){
        int row = j0 + jb*8 + u;
        float* o = out + ((size_t)b*Nq + row)*256 + h*32 + kbase;
        float vals[8];
        #pragma unroll
        for (int v=0;v<8;v++) vals[v] = gelu_f(acc[u][v]);
        *reinterpret_cast<float4*>(o)   = make_float4(vals[0],vals[1],vals[2],vals[3]);
        *reinterpret_cast<float4*>(o+4) = make_float4(vals[4],vals[5],vals[6],vals[7]);
    }
}

// ---------------------------------------------------------------------------
// Final dense 256 -> 1 (one warp per row)
// ---------------------------------------------------------------------------
__global__ void final_dense_kernel(const float* __restrict__ hin,
                                   const float* __restrict__ w,
                                   const float* __restrict__ bias,
                                   float* __restrict__ out){
    int warp = threadIdx.x >> 5;
    int lane = threadIdx.x & 31;
    int row = blockIdx.x * 8 + warp;
    const float* hr = hin + (size_t)row * 256;
    float s = 0.f;
    #pragma unroll
    for (int i = 0; i < 8; i++) s += hr[lane + 32*i] * w[lane + 32*i];
    #pragma unroll
    for (int off = 16; off; off >>= 1) s += __shfl_xor_sync(0xffffffff, s, off);
    if (lane == 0) out[row] = s + bias[0];
}

// ---------------------------------------------------------------------------
// Host orchestration
// ---------------------------------------------------------------------------
extern "C" void kernel_launch(void* const* d_in, const int* in_sizes, int n_in,
                              void* d_out, int out_size){
    const float* x      = (const float*)d_in[0];
    const float* m_down = (const float*)d_in[1];
    const float* m_p[2] = {(const float*)d_in[2], (const float*)d_in[3]};
    const float* m_up   = (const float*)d_in[4];
    const float* en_w   = (const float*)d_in[5];
    const float* en_b   = (const float*)d_in[6];
    const float* down_r = (const float*)d_in[7];
    const float* down_w = (const float*)d_in[8];
    const float* pa_r[2]= {(const float*)d_in[9],  (const float*)d_in[17]};
    const float* pa_w[2]= {(const float*)d_in[10], (const float*)d_in[18]};
    const float* f1w[2] = {(const float*)d_in[11], (const float*)d_in[19]};
    const float* f1b[2] = {(const float*)d_in[12], (const float*)d_in[20]};
    const float* f2w[2] = {(const float*)d_in[13], (const float*)d_in[21]};
    const float* f2b[2] = {(const float*)d_in[14], (const float*)d_in[22]};
    const float* rw[2]  = {(const float*)d_in[15], (const float*)d_in[23]};
    const float* rb[2]  = {(const float*)d_in[16], (const float*)d_in[24]};
    const float* up_r   = (const float*)d_in[25];
    const float* up_w   = (const float*)d_in[26];
    const float* de1w   = (const float*)d_in[27];
    const float* de1b   = (const float*)d_in[28];
    const float* de2w   = (const float*)d_in[29];
    const float* de2b   = (const float*)d_in[30];
    float* outp = (float*)d_out;

    float *b0, *b1, *lat, *pa, *t1, *t3, *wcat, *smin, *sinv, *sthr;
    cudaGetSymbolAddress((void**)&b0,   g_big0);
    cudaGetSymbolAddress((void**)&b1,   g_big1);
    cudaGetSymbolAddress((void**)&lat,  g_lat);
    cudaGetSymbolAddress((void**)&pa,   g_pa);
    cudaGetSymbolAddress((void**)&t1,   g_t1);
    cudaGetSymbolAddress((void**)&t3,   g_t3);
    cudaGetSymbolAddress((void**)&wcat, g_wcat);
    cudaGetSymbolAddress((void**)&smin, g_smin);
    cudaGetSymbolAddress((void**)&sinv, g_sinv);
    cudaGetSymbolAddress((void**)&sthr, g_sthr);

    // 1. encoder: h0 = gelu(x @ en_w + en_b)   -> b0  [B*NFULL, 256]
    encoder_kernel<<<MBIG, 256>>>(x, en_w, en_b, b0);

    // 2. down pos_att (global)
    repack_w_kernel<<<256, 256>>>(down_w, wcat);
    gemm256_kernel<false,false,false><<<MBIG/64, 256>>>(b0, wcat, nullptr, nullptr, b1); // value
    stats_global_kernel<<<HEADS*NLAT, 256, NFULL*4>>>(m_down, down_r, smin, sinv, sthr, NLAT, NFULL);
    attn_apply_kernel<<<dim3(NLAT/64, HEADS), 256>>>(m_down, down_r, smin, sinv, sthr,
                                                     b1, lat, NLAT, NFULL);

    // 3. latent blocks (local, 30th percentile)
    for (int blk = 0; blk < 2; blk++){
        stats_local_kernel<<<HEADS*NLAT, 256>>>(m_p[blk], pa_r[blk], smin, sinv, sthr, NLAT);
        repack_w_kernel<<<256, 256>>>(pa_w[blk], wcat);
        gemm256_kernel<false,false,false><<<MLAT/64, 256>>>(lat, wcat, nullptr, nullptr, t1); // value
        attn_apply_kernel<<<dim3(NLAT/64, HEADS), 256>>>(m_p[blk], pa_r[blk], smin, sinv, sthr,
                                                         t1, pa, NLAT, NLAT);
        gemm256_kernel<true,true,false><<<MLAT/64, 256>>>(pa, f1w[blk], f1b[blk], nullptr, t1); // gelu(fc1)
        gemm256_kernel<true,false,false><<<MLAT/64, 256>>>(lat, rw[blk], rb[blk], nullptr, t3); // residual
        gemm256_kernel<true,true,true><<<MLAT/64, 256>>>(t1, f2w[blk], f2b[blk], t3, lat);      // gelu(fc2+res)
    }

    // 4. up pos_att (global)
    stats_global_kernel<<<HEADS*NFULL, 256, NLAT*4>>>(m_up, up_r, smin, sinv, sthr, NFULL, NLAT);
    repack_w_kernel<<<256, 256>>>(up_w, wcat);
    gemm256_kernel<false,false,false><<<MLAT/64, 256>>>(lat, wcat, nullptr, nullptr, t1);  // value
    attn_apply_kernel<<<dim3(NFULL/64, HEADS), 256>>>(m_up, up_r, smin, sinv, sthr,
                                                      t1, b0, NFULL, NLAT);

    // 5. decoder
    gemm256_kernel<true,true,false><<<MBIG/64, 256>>>(b0, de1w, de1b, nullptr, b1);  // gelu(de_fc1)
    final_dense_kernel<<<MBIG/8, 256>>>(b1, de2w, de2b, outp);                       // de_fc2
}

// round 11
// speedup vs baseline: 2.1284x; 2.1284x over previous
#include <cuda_runtime.h>
#include <cuda_bf16.h>
#include <mma.h>
#include <math.h>
#include <stdint.h>

using namespace nvcuda;

#define Bq      8
#define NFULL   4096
#define NLAT    1024
#define HEADS   8
#define MBIG    (Bq*NFULL)   // 32768
#define MLAT    (Bq*NLAT)    // 8192

// ---------------------------------------------------------------------------
// Scratch (device globals; no allocation allowed)
// ---------------------------------------------------------------------------
__device__ __nv_bfloat16 g_b0h[MBIG*256], g_b0l[MBIG*256];
__device__ float         g_b1[MBIG*256];
__device__ __nv_bfloat16 g_lath[MLAT*256], g_latl[MLAT*256];
__device__ __nv_bfloat16 g_pah[MLAT*256],  g_pal[MLAT*256];
__device__ __nv_bfloat16 g_t1h[MLAT*256],  g_t1l[MLAT*256];
__device__ float         g_t3[MLAT*256];
__device__ __nv_bfloat16 g_vh[HEADS*256*NFULL], g_vl[HEADS*256*NFULL];
__device__ __nv_bfloat16 g_wh[256*256], g_wl[256*256];
__device__ float g_smin[HEADS*NFULL], g_sinv[HEADS*NFULL], g_sthr[HEADS*NFULL];

// ---------------------------------------------------------------------------
// Helpers
// ---------------------------------------------------------------------------
__device__ __forceinline__ uint32_t smem_u32(const void* p){
    uint32_t a;
    asm("{ .reg .u64 t; cvta.to.shared.u64 t, %1; cvt.u32.u64 %0, t; }" : "=r"(a) : "l"(p));
    return a;
}
#define CP_ASYNC16(dst, src) \
    asm volatile("cp.async.ca.shared.global [%0], [%1], 16;" :: "r"(dst), "l"(src))
#define CP_COMMIT() asm volatile("cp.async.commit_group;" ::: "memory")
#define CP_WAIT(N)  asm volatile("cp.async.wait_group %0;" :: "n"(N) : "memory")

__device__ __forceinline__ void split_pack(float v0, float v1, uint32_t& h, uint32_t& l){
    float h0 = __bfloat162float(__float2bfloat16(v0));
    float h1 = __bfloat162float(__float2bfloat16(v1));
    __nv_bfloat162 hh = __floats2bfloat162_rn(v0, v1);
    __nv_bfloat162 ll = __floats2bfloat162_rn(v0 - h0, v1 - h1);
    h = reinterpret_cast<uint32_t&>(hh);
    l = reinterpret_cast<uint32_t&>(ll);
}
__device__ __forceinline__ float gelu_f(float v){
    float t = tanhf(0.7978845608028654f * (v + 0.044715f * v * v * v));
    return 0.5f * v * (1.0f + t);
}
__device__ __forceinline__ float scale_from_r(float r){
    const float A = 0.7853980848576320f;
    return tanf(A * (1.0f + sinf(r)));
}

// ---------------------------------------------------------------------------
// Encoder: gelu(x @ W[4,256] + b) -> bf16 hi/lo planes
// ---------------------------------------------------------------------------
__global__ void encoder_kernel(const float* __restrict__ x,
                               const float* __restrict__ W,
                               const float* __restrict__ bias,
                               __nv_bfloat16* __restrict__ oh,
                               __nv_bfloat16* __restrict__ ol){
    int m = blockIdx.x, c = threadIdx.x;
    const float* xr = x + (size_t)m * 4;
    float v = bias[c] + xr[0]*W[c] + xr[1]*W[256+c] + xr[2]*W[512+c] + xr[3]*W[768+c];
    v = gelu_f(v);
    __nv_bfloat16 hb = __float2bfloat16(v);
    oh[(size_t)m*256 + c] = hb;
    ol[(size_t)m*256 + c] = __float2bfloat16(v - __bfloat162float(hb));
}

// ---------------------------------------------------------------------------
// Weight split kernels: output B-layout [n][k]
// ---------------------------------------------------------------------------
__global__ void split_dense_w(const float* __restrict__ W,
                              __nv_bfloat16* __restrict__ oh, __nv_bfloat16* __restrict__ ol){
    int idx = blockIdx.x*256 + threadIdx.x;
    int c = idx >> 8, k = idx & 255;
    float v = W[k*256 + c];
    __nv_bfloat16 hb = __float2bfloat16(v);
    oh[idx] = hb; ol[idx] = __float2bfloat16(v - __bfloat162float(hb));
}
__global__ void split_attn_w(const float* __restrict__ w,
                             __nv_bfloat16* __restrict__ oh, __nv_bfloat16* __restrict__ ol){
    int idx = blockIdx.x*256 + threadIdx.x;
    int c = idx >> 8, k = idx & 255;
    int hh = c >> 5, kv = c & 31;
    float v = w[hh*256*32 + k*32 + kv];
    __nv_bfloat16 hb = __float2bfloat16(v);
    oh[idx] = hb; ol[idx] = __float2bfloat16(v - __bfloat162float(hb));
}

// ---------------------------------------------------------------------------
// Softmax stats (unchanged from passing kernel)
// ---------------------------------------------------------------------------
__global__ void stats_global_kernel(const float* __restrict__ m, const float* __restrict__ r,
                                    float* __restrict__ sdmin, float* __restrict__ invden,
                                    float* __restrict__ thr, int Nq, int Nk){
    extern __shared__ float sbuf[];
    __shared__ float red[256];
    int row = blockIdx.x;
    int h = row / Nq;
    float scale = scale_from_r(r[h]);
    const float* mr = m + (size_t)row * Nk;
    float lmin = 3.402823466e38f;
    for (int i = threadIdx.x; i < Nk; i += 256){
        float sd = mr[i] * scale; sbuf[i] = sd; lmin = fminf(lmin, sd);
    }
    red[threadIdx.x] = lmin; __syncthreads();
    for (int s=128; s>0; s>>=1){
        if (threadIdx.x < s) red[threadIdx.x] = fminf(red[threadIdx.x], red[threadIdx.x+s]);
        __syncthreads();
    }
    float mn = red[0]; __syncthreads();
    float ls = 0.f;
    for (int i = threadIdx.x; i < Nk; i += 256) ls += __expf(mn - sbuf[i]);
    red[threadIdx.x] = ls; __syncthreads();
    for (int s=128; s>0; s>>=1){
        if (threadIdx.x < s) red[threadIdx.x] += red[threadIdx.x+s];
        __syncthreads();
    }
    if (threadIdx.x == 0){
        sdmin[row] = mn; invden[row] = 1.0f/red[0]; thr[row] = __int_as_float(0x7f800000);
    }
}
__global__ void stats_local_kernel(const float* __restrict__ m, const float* __restrict__ r,
                                   float* __restrict__ sdmin, float* __restrict__ invden,
                                   float* __restrict__ thr, int Nq){
    __shared__ float s[1024];
    __shared__ float red[256];
    int row = blockIdx.x;
    int h = row / Nq;
    float scale = scale_from_r(r[h]);
    const float* mr = m + (size_t)row * 1024;
    for (int i = threadIdx.x; i < 1024; i += 256) s[i] = mr[i] * scale;
    __syncthreads();
    for (int k = 2; k <= 1024; k <<= 1){
        for (int j = k >> 1; j > 0; j >>= 1){
            for (int i = threadIdx.x; i < 1024; i += 256){
                int ixj = i ^ j;
                if (ixj > i){
                    bool up = ((i & k) == 0);
                    float a = s[i], b = s[ixj];
                    if ((a > b) == up){ s[i] = b; s[ixj] = a; }
                }
            }
            __syncthreads();
        }
    }
    float pos = 1023.0f * 0.30f;
    int lo = (int)pos;
    float fr = pos - (float)lo;
    float th = s[lo] + fr * (s[lo+1] - s[lo]);
    float mn = s[0];
    float ls = 0.f;
    for (int i = threadIdx.x; i < 1024; i += 256){
        float v = s[i];
        if (v <= th) ls += __expf(mn - v);
    }
    red[threadIdx.x] = ls; __syncthreads();
    for (int st=128; st>0; st>>=1){
        if (threadIdx.x < st) red[threadIdx.x] += red[threadIdx.x+st];
        __syncthreads();
    }
    if (threadIdx.x == 0){ sdmin[row]=mn; invden[row]=1.0f/red[0]; thr[row]=th; }
}

// ---------------------------------------------------------------------------
// Unified WMMA bf16 hi/lo-split GEMM.  Tile 128(M) x 128(N), K chunks of 32,
// cp.async double-buffered.  8 warps = 4(M) x 2(N); warp tile 32x64.
// AMODE 0: A = pre-split bf16 planes [M][256]
// AMODE 1: A = softmax P on the fly from m_dist + stats
// EMODE 0: +bias -> f32            1: +bias,gelu -> split planes
//       2: +bias,gelu -> f32       3: +bias+addin,gelu -> split planes
//       4: transpose -> V[h][(b,kv)][n] split planes
//       5: gelu -> split planes scattered to [(b,row)][h*32+k]
// ---------------------------------------------------------------------------
#define ASTRIDE 40
#define PLANEB  (128*ASTRIDE*2)        // 10240 bytes per plane
#define STAGEB  (4*PLANEB)             // 40960 bytes per stage
#define SMEMSZ  (2*STAGEB)             // 81920

template<int AMODE, int EMODE>
__global__ __launch_bounds__(256)
void wmma_gemm(const __nv_bfloat16* __restrict__ Ah, const __nv_bfloat16* __restrict__ Al,
               const float* __restrict__ mdist, const float* __restrict__ rr,
               const float* __restrict__ psmin, const float* __restrict__ psinv,
               const float* __restrict__ psthr, int Nq,
               const __nv_bfloat16* __restrict__ Bh, const __nv_bfloat16* __restrict__ Bl,
               int K,
               const float* __restrict__ bias, const float* __restrict__ addin,
               float* __restrict__ outf, __nv_bfloat16* __restrict__ outh,
               __nv_bfloat16* __restrict__ outl, int nper)
{
    extern __shared__ char sm[];
    __shared__ float s_mn[128], s_iv[128], s_th[128];

    int tid = threadIdx.x;
    int m0 = blockIdx.x * 128, yb = blockIdx.y * 128, h = blockIdx.z;

    float scale = 0.f;
    const float* mrow = nullptr;
    const __nv_bfloat16 *pa_h = nullptr, *pa_l = nullptr;
    if (AMODE == 1){
        scale = scale_from_r(rr[h]);
        if (tid < 128){
            int rg = h*Nq + m0 + tid;
            s_mn[tid] = psmin[rg]; s_iv[tid] = psinv[rg]; s_th[tid] = psthr[rg];
        }
        mrow = mdist + ((size_t)h*Nq + m0) * K;
    } else {
        pa_h = Ah + (size_t)m0 * 256;
        pa_l = Al + (size_t)m0 * 256;
    }
    const __nv_bfloat16* pb_h = Bh + (size_t)(h*256 + yb) * K;
    const __nv_bfloat16* pb_l = Bl + (size_t)(h*256 + yb) * K;
    if (AMODE == 1) __syncthreads();

    int row  = tid >> 1;
    int half = tid & 1;

    auto produce = [&](int c, int s){
        char* base = sm + s*STAGEB;
        char* dAh = base;
        char* dAl = base + PLANEB;
        char* dBh = base + 2*PLANEB;
        char* dBl = base + 3*PLANEB;
        int n0 = c*32;
        uint32_t sA = smem_u32(base) + (uint32_t)(row*(ASTRIDE*2) + half*32);
        if (AMODE == 0){
            const __nv_bfloat16* sh = pa_h + (size_t)row*256 + n0 + half*16;
            const __nv_bfloat16* sl = pa_l + (size_t)row*256 + n0 + half*16;
            CP_ASYNC16(sA,                    sh);
            CP_ASYNC16(sA + 16,               sh + 8);
            CP_ASYNC16(sA + PLANEB,           sl);
            CP_ASYNC16(sA + PLANEB + 16,      sl + 8);
        } else {
            const float* mr = mrow + (size_t)row*K + n0 + half*16;
            float mn = s_mn[row], iv = s_iv[row], th = s_th[row];
            float p[16];
            #pragma unroll
            for (int i=0;i<4;i++){
                float4 a = *(const float4*)(mr + i*4);
                float s0;
                s0=a.x*scale; p[i*4+0]=(s0<=th)?__expf(mn-s0)*iv:0.f;
                s0=a.y*scale; p[i*4+1]=(s0<=th)?__expf(mn-s0)*iv:0.f;
                s0=a.z*scale; p[i*4+2]=(s0<=th)?__expf(mn-s0)*iv:0.f;
                s0=a.w*scale; p[i*4+3]=(s0<=th)?__expf(mn-s0)*iv:0.f;
            }
            uint4 uh0, ul0, uh1, ul1;
            split_pack(p[0],p[1],uh0.x,ul0.x);  split_pack(p[2],p[3],uh0.y,ul0.y);
            split_pack(p[4],p[5],uh0.z,ul0.z);  split_pack(p[6],p[7],uh0.w,ul0.w);
            split_pack(p[8],p[9],uh1.x,ul1.x);  split_pack(p[10],p[11],uh1.y,ul1.y);
            split_pack(p[12],p[13],uh1.z,ul1.z);split_pack(p[14],p[15],uh1.w,ul1.w);
            *(uint4*)(dAh + row*(ASTRIDE*2) + half*32)      = uh0;
            *(uint4*)(dAh + row*(ASTRIDE*2) + half*32 + 16) = uh1;
            *(uint4*)(dAl + row*(ASTRIDE*2) + half*32)      = ul0;
            *(uint4*)(dAl + row*(ASTRIDE*2) + half*32 + 16) = ul1;
        }
        const __nv_bfloat16* sh = pb_h + (size_t)row*K + n0 + half*16;
        const __nv_bfloat16* sl = pb_l + (size_t)row*K + n0 + half*16;
        uint32_t sB = sA + 2*PLANEB;
        CP_ASYNC16(sB,               sh);
        CP_ASYNC16(sB + 16,          sh + 8);
        CP_ASYNC16(sB + PLANEB,      sl);
        CP_ASYNC16(sB + PLANEB + 16, sl + 8);
    };

    int wid = tid >> 5;
    int wm = wid >> 1, wn = wid & 1;

    wmma::fragment<wmma::accumulator, 16,16,16, float> acc[2][4];
    #pragma unroll
    for (int im=0;im<2;im++)
        #pragma unroll
        for (int in=0;in<4;in++) wmma::fill_fragment(acc[im][in], 0.0f);

    int nch = K >> 5;
    produce(0, 0);
    CP_COMMIT();

    for (int c = 0; c < nch; c++){
        if (c + 1 < nch){ produce(c+1, (c+1)&1); CP_COMMIT(); CP_WAIT(1); }
        else            { CP_WAIT(0); }
        __syncthreads();

        const char* base = sm + (c&1)*STAGEB;
        const __nv_bfloat16* As_h = (const __nv_bfloat16*)(base);
        const __nv_bfloat16* As_l = (const __nv_bfloat16*)(base + PLANEB);
        const __nv_bfloat16* Bs_h = (const __nv_bfloat16*)(base + 2*PLANEB);
        const __nv_bfloat16* Bs_l = (const __nv_bfloat16*)(base + 3*PLANEB);

        #pragma unroll
        for (int kk = 0; kk < 32; kk += 16){
            wmma::fragment<wmma::matrix_a, 16,16,16, __nv_bfloat16, wmma::row_major> ah[2], al[2];
            #pragma unroll
            for (int im=0;im<2;im++){
                wmma::load_matrix_sync(ah[im], As_h + (wm*32 + im*16)*ASTRIDE + kk, ASTRIDE);
                wmma::load_matrix_sync(al[im], As_l + (wm*32 + im*16)*ASTRIDE + kk, ASTRIDE);
            }
            #pragma unroll
            for (int in=0;in<4;in++){
                int n0 = wn*64 + in*16;
                wmma::fragment<wmma::matrix_b, 16,16,16, __nv_bfloat16, wmma::col_major> bh, bl;
                wmma::load_matrix_sync(bh, Bs_h + n0*ASTRIDE + kk, ASTRIDE);
                wmma::load_matrix_sync(bl, Bs_l + n0*ASTRIDE + kk, ASTRIDE);
                #pragma unroll
                for (int im=0;im<2;im++){
                    wmma::mma_sync(acc[im][in], ah[im], bh, acc[im][in]);
                    wmma::mma_sync(acc[im][in], ah[im], bl, acc[im][in]);
                    wmma::mma_sync(acc[im][in], al[im], bh, acc[im][in]);
                }
            }
        }
        __syncthreads();
    }

    // Epilogue: dump fp32 tile to smem, post-process
    float* Sf = (float*)sm;                      // 128 x 136
    #pragma unroll
    for (int im=0;im<2;im++)
        #pragma unroll
        for (int in=0;in<4;in++)
            wmma::store_matrix_sync(Sf + (wm*32 + im*16)*136 + wn*64 + in*16,
                                    acc[im][in], 136, wmma::mem_row_major);
    __syncthreads();

    if (EMODE == 4){
        int j = tid >> 1, mh = tid & 1;          // col j, row half mh
        int cg = yb + j;
        int bidx = m0 / nper;
        size_t rowo = ((size_t)(cg>>5)*256 + bidx*32 + (cg&31)) * (size_t)nper
                    + (size_t)(m0 - bidx*nper) + mh*64;
        #pragma unroll
        for (int i=0;i<64;i+=2){
            float v0 = Sf[(mh*64+i  )*136 + j];
            float v1 = Sf[(mh*64+i+1)*136 + j];
            uint32_t uh, ul; split_pack(v0, v1, uh, ul);
            *(uint32_t*)(outh + rowo + i) = uh;
            *(uint32_t*)(outl + rowo + i) = ul;
        }
    } else {
        int mm = tid >> 1, ch0 = (tid & 1)*64;
        #pragma unroll
        for (int j=0;j<64;j+=2){
            int c1 = ch0 + j;
            int gc = yb + c1;
            float v0 = Sf[mm*136 + c1], v1 = Sf[mm*136 + c1 + 1];
            if (EMODE==0||EMODE==1||EMODE==2||EMODE==3){
                v0 += bias[gc]; v1 += bias[gc+1];
            }
            size_t ob;
            if (EMODE == 5){
                int b = gc >> 5, k = gc & 31;
                ob = ((size_t)b*nper + m0 + mm)*256 + (size_t)h*32 + k;
            } else {
                ob = (size_t)(m0 + mm)*256 + gc;
            }
            if (EMODE==3){ v0 += addin[ob]; v1 += addin[ob+1]; }
            if (EMODE==1||EMODE==2||EMODE==3||EMODE==5){ v0 = gelu_f(v0); v1 = gelu_f(v1); }
            if (EMODE==0||EMODE==2){
                outf[ob] = v0; outf[ob+1] = v1;
            } else {
                uint32_t uh, ul; split_pack(v0, v1, uh, ul);
                *(uint32_t*)(outh + ob) = uh;
                *(uint32_t*)(outl + ob) = ul;
            }
        }
    }
}

// ---------------------------------------------------------------------------
// Final dense 256 -> 1
// ---------------------------------------------------------------------------
__global__ void final_dense_kernel(const float* __restrict__ hin,
                                   const float* __restrict__ w,
                                   const float* __restrict__ bias,
                                   float* __restrict__ out){
    int warp = threadIdx.x >> 5, lane = threadIdx.x & 31;
    int row = blockIdx.x * 8 + warp;
    const float* hr = hin + (size_t)row * 256;
    float s = 0.f;
    #pragma unroll
    for (int i = 0; i < 8; i++) s += hr[lane + 32*i] * w[lane + 32*i];
    #pragma unroll
    for (int off = 16; off; off >>= 1) s += __shfl_xor_sync(0xffffffff, s, off);
    if (lane == 0) out[row] = s + bias[0];
}

// ---------------------------------------------------------------------------
// Host orchestration
// ---------------------------------------------------------------------------
extern "C" void kernel_launch(void* const* d_in, const int* in_sizes, int n_in,
                              void* d_out, int out_size){
    const float* x      = (const float*)d_in[0];
    const float* m_down = (const float*)d_in[1];
    const float* m_p[2] = {(const float*)d_in[2], (const float*)d_in[3]};
    const float* m_up   = (const float*)d_in[4];
    const float* en_w   = (const float*)d_in[5];
    const float* en_b   = (const float*)d_in[6];
    const float* down_r = (const float*)d_in[7];
    const float* down_w = (const float*)d_in[8];
    const float* pa_r[2]= {(const float*)d_in[9],  (const float*)d_in[17]};
    const float* pa_w[2]= {(const float*)d_in[10], (const float*)d_in[18]};
    const float* f1w[2] = {(const float*)d_in[11], (const float*)d_in[19]};
    const float* f1b[2] = {(const float*)d_in[12], (const float*)d_in[20]};
    const float* f2w[2] = {(const float*)d_in[13], (const float*)d_in[21]};
    const float* f2b[2] = {(const float*)d_in[14], (const float*)d_in[22]};
    const float* rw[2]  = {(const float*)d_in[15], (const float*)d_in[23]};
    const float* rb[2]  = {(const float*)d_in[16], (const float*)d_in[24]};
    const float* up_r   = (const float*)d_in[25];
    const float* up_w   = (const float*)d_in[26];
    const float* de1w   = (const float*)d_in[27];
    const float* de1b   = (const float*)d_in[28];
    const float* de2w   = (const float*)d_in[29];
    const float* de2b   = (const float*)d_in[30];
    float* outp = (float*)d_out;

    __nv_bfloat16 *b0h,*b0l,*lath,*latl,*pah,*pal,*t1h,*t1l,*vh,*vl,*wh,*wl;
    float *b1,*t3,*smin,*sinv,*sthr;
    cudaGetSymbolAddress((void**)&b0h, g_b0h);  cudaGetSymbolAddress((void**)&b0l, g_b0l);
    cudaGetSymbolAddress((void**)&b1,  g_b1);
    cudaGetSymbolAddress((void**)&lath,g_lath); cudaGetSymbolAddress((void**)&latl,g_latl);
    cudaGetSymbolAddress((void**)&pah, g_pah);  cudaGetSymbolAddress((void**)&pal, g_pal);
    cudaGetSymbolAddress((void**)&t1h, g_t1h);  cudaGetSymbolAddress((void**)&t1l, g_t1l);
    cudaGetSymbolAddress((void**)&t3,  g_t3);
    cudaGetSymbolAddress((void**)&vh,  g_vh);   cudaGetSymbolAddress((void**)&vl,  g_vl);
    cudaGetSymbolAddress((void**)&wh,  g_wh);   cudaGetSymbolAddress((void**)&wl,  g_wl);
    cudaGetSymbolAddress((void**)&smin,g_smin); cudaGetSymbolAddress((void**)&sinv,g_sinv);
    cudaGetSymbolAddress((void**)&sthr,g_sthr);

    cudaFuncSetAttribute((const void*)wmma_gemm<0,4>, cudaFuncAttributeMaxDynamicSharedMemorySize, SMEMSZ);
    cudaFuncSetAttribute((const void*)wmma_gemm<1,5>, cudaFuncAttributeMaxDynamicSharedMemorySize, SMEMSZ);
    cudaFuncSetAttribute((const void*)wmma_gemm<0,1>, cudaFuncAttributeMaxDynamicSharedMemorySize, SMEMSZ);
    cudaFuncSetAttribute((const void*)wmma_gemm<0,0>, cudaFuncAttributeMaxDynamicSharedMemorySize, SMEMSZ);
    cudaFuncSetAttribute((const void*)wmma_gemm<0,3>, cudaFuncAttributeMaxDynamicSharedMemorySize, SMEMSZ);
    cudaFuncSetAttribute((const void*)wmma_gemm<0,2>, cudaFuncAttributeMaxDynamicSharedMemorySize, SMEMSZ);

    // 1. encoder -> b0 hi/lo planes
    encoder_kernel<<<MBIG, 256>>>(x, en_w, en_b, b0h, b0l);

    // 2. down pos_att (global)
    split_attn_w<<<256, 256>>>(down_w, wh, wl);
    wmma_gemm<0,4><<<dim3(MBIG/128,2,1), 256, SMEMSZ>>>(
        b0h, b0l, nullptr, nullptr, nullptr, nullptr, nullptr, 0,
        wh, wl, 256, nullptr, nullptr, nullptr, vh, vl, NFULL);
    stats_global_kernel<<<HEADS*NLAT, 256, NFULL*4>>>(m_down, down_r, smin, sinv, sthr, NLAT, NFULL);
    wmma_gemm<1,5><<<dim3(NLAT/128,2,HEADS), 256, SMEMSZ>>>(
        nullptr, nullptr, m_down, down_r, smin, sinv, sthr, NLAT,
        vh, vl, NFULL, nullptr, nullptr, nullptr, lath, latl, NLAT);

    // 3. latent blocks (local, 30th percentile)
    for (int blk = 0; blk < 2; blk++){
        stats_local_kernel<<<HEADS*NLAT, 256>>>(m_p[blk], pa_r[blk], smin, sinv, sthr, NLAT);
        split_attn_w<<<256, 256>>>(pa_w[blk], wh, wl);
        wmma_gemm<0,4><<<dim3(MLAT/128,2,1), 256, SMEMSZ>>>(
            lath, latl, nullptr, nullptr, nullptr, nullptr, nullptr, 0,
            wh, wl, 256, nullptr, nullptr, nullptr, vh, vl, NLAT);
        wmma_gemm<1,5><<<dim3(NLAT/128,2,HEADS), 256, SMEMSZ>>>(
            nullptr, nullptr, m_p[blk], pa_r[blk], smin, sinv, sthr, NLAT,
            vh, vl, NLAT, nullptr, nullptr, nullptr, pah, pal, NLAT);
        split_dense_w<<<256, 256>>>(f1w[blk], wh, wl);
        wmma_gemm<0,1><<<dim3(MLAT/128,2,1), 256, SMEMSZ>>>(
            pah, pal, nullptr, nullptr, nullptr, nullptr, nullptr, 0,
            wh, wl, 256, f1b[blk], nullptr, nullptr, t1h, t1l, 0);
        split_dense_w<<<256, 256>>>(rw[blk], wh, wl);
        wmma_gemm<0,0><<<dim3(MLAT/128,2,1), 256, SMEMSZ>>>(
            lath, latl, nullptr, nullptr, nullptr, nullptr, nullptr, 0,
            wh, wl, 256, rb[blk], nullptr, t3, nullptr, nullptr, 0);
        split_dense_w<<<256, 256>>>(f2w[blk], wh, wl);
        wmma_gemm<0,3><<<dim3(MLAT/128,2,1), 256, SMEMSZ>>>(
            t1h, t1l, nullptr, nullptr, nullptr, nullptr, nullptr, 0,
            wh, wl, 256, f2b[blk], t3, nullptr, lath, latl, 0);
    }

    // 4. up pos_att (global)
    stats_global_kernel<<<HEADS*NFULL, 256, NLAT*4>>>(m_up, up_r, smin, sinv, sthr, NFULL, NLAT);
    split_attn_w<<<256, 256>>>(up_w, wh, wl);
    wmma_gemm<0,4><<<dim3(MLAT/128,2,1), 256, SMEMSZ>>>(
        lath, latl, nullptr, nullptr, nullptr, nullptr, nullptr, 0,
        wh, wl, 256, nullptr, nullptr, nullptr, vh, vl, NLAT);
    wmma_gemm<1,5><<<dim3(NFULL/128,2,HEADS), 256, SMEMSZ>>>(
        nullptr, nullptr, m_up, up_r, smin, sinv, sthr, NFULL,
        vh, vl, NLAT, nullptr, nullptr, nullptr, b0h, b0l, NFULL);

    // 5. decoder
    split_dense_w<<<256, 256>>>(de1w, wh, wl);
    wmma_gemm<0,2><<<dim3(MBIG/128,2,1), 256, SMEMSZ>>>(
        b0h, b0l, nullptr, nullptr, nullptr, nullptr, nullptr, 0,
        wh, wl, 256, de1b, nullptr, b1, nullptr, nullptr, 0);
    final_dense_kernel<<<MBIG/8, 256>>>(b1, de2w, de2b, outp);
}

// round 15
// speedup vs baseline: 2.6516x; 1.2458x over previous
#include <cuda_runtime.h>
#include <cuda_bf16.h>
#include <mma.h>
#include <math.h>
#include <stdint.h>

using namespace nvcuda;

#define Bq      8
#define NFULL   4096
#define NLAT    1024
#define HEADS   8
#define MBIG    (Bq*NFULL)   // 32768
#define MLAT    (Bq*NLAT)    // 8192

// ---------------------------------------------------------------------------
// Scratch (device globals; no allocation allowed)
// ---------------------------------------------------------------------------
__device__ __nv_bfloat16 g_b0h[MBIG*256], g_b0l[MBIG*256];
__device__ float         g_b1[MBIG*256];
__device__ __nv_bfloat16 g_lath[MLAT*256], g_latl[MLAT*256];
__device__ __nv_bfloat16 g_pah[MLAT*256],  g_pal[MLAT*256];
__device__ __nv_bfloat16 g_t1h[MLAT*256],  g_t1l[MLAT*256];
__device__ float         g_t3[MLAT*256];
__device__ __nv_bfloat16 g_vh[HEADS*256*NFULL], g_vl[HEADS*256*NFULL];
__device__ __nv_bfloat16 g_wh[256*256], g_wl[256*256];
__device__ __nv_bfloat16 g_ph[HEADS*NFULL*NLAT], g_pl[HEADS*NFULL*NLAT];  // P planes

// ---------------------------------------------------------------------------
// Helpers
// ---------------------------------------------------------------------------
__device__ __forceinline__ uint32_t smem_u32(const void* p){
    uint32_t a;
    asm("{ .reg .u64 t; cvta.to.shared.u64 t, %1; cvt.u32.u64 %0, t; }" : "=r"(a) : "l"(p));
    return a;
}
#define CP_ASYNC16(dst, src) \
    asm volatile("cp.async.ca.shared.global [%0], [%1], 16;" :: "r"(dst), "l"(src))
#define CP_COMMIT() asm volatile("cp.async.commit_group;" ::: "memory")
#define CP_WAIT(N)  asm volatile("cp.async.wait_group %0;" :: "n"(N) : "memory")

__device__ __forceinline__ void split_pack(float v0, float v1, uint32_t& h, uint32_t& l){
    float h0 = __bfloat162float(__float2bfloat16(v0));
    float h1 = __bfloat162float(__float2bfloat16(v1));
    __nv_bfloat162 hh = __floats2bfloat162_rn(v0, v1);
    __nv_bfloat162 ll = __floats2bfloat162_rn(v0 - h0, v1 - h1);
    h = reinterpret_cast<uint32_t&>(hh);
    l = reinterpret_cast<uint32_t&>(ll);
}
__device__ __forceinline__ float gelu_f(float v){
    float t = tanhf(0.7978845608028654f * (v + 0.044715f * v * v * v));
    return 0.5f * v * (1.0f + t);
}
__device__ __forceinline__ float scale_from_r(float r){
    const float A = 0.7853980848576320f;
    return tanf(A * (1.0f + sinf(r)));
}
__device__ __forceinline__ float key_to_f(uint32_t u){
    uint32_t b = (u & 0x80000000u) ? (u & 0x7FFFFFFFu) : ~u;
    return __uint_as_float(b);
}

// ---------------------------------------------------------------------------
// Encoder: gelu(x @ W[4,256] + b) -> bf16 hi/lo planes
// ---------------------------------------------------------------------------
__global__ void encoder_kernel(const float* __restrict__ x,
                               const float* __restrict__ W,
                               const float* __restrict__ bias,
                               __nv_bfloat16* __restrict__ oh,
                               __nv_bfloat16* __restrict__ ol){
    int m = blockIdx.x, c = threadIdx.x;
    const float* xr = x + (size_t)m * 4;
    float v = bias[c] + xr[0]*W[c] + xr[1]*W[256+c] + xr[2]*W[512+c] + xr[3]*W[768+c];
    v = gelu_f(v);
    __nv_bfloat16 hb = __float2bfloat16(v);
    oh[(size_t)m*256 + c] = hb;
    ol[(size_t)m*256 + c] = __float2bfloat16(v - __bfloat162float(hb));
}

// ---------------------------------------------------------------------------
// Weight split kernels: output B-layout [n][k]
// ---------------------------------------------------------------------------
__global__ void split_dense_w(const float* __restrict__ W,
                              __nv_bfloat16* __restrict__ oh, __nv_bfloat16* __restrict__ ol){
    int idx = blockIdx.x*256 + threadIdx.x;
    int c = idx >> 8, k = idx & 255;
    float v = W[k*256 + c];
    __nv_bfloat16 hb = __float2bfloat16(v);
    oh[idx] = hb; ol[idx] = __float2bfloat16(v - __bfloat162float(hb));
}
__global__ void split_attn_w(const float* __restrict__ w,
                             __nv_bfloat16* __restrict__ oh, __nv_bfloat16* __restrict__ ol){
    int idx = blockIdx.x*256 + threadIdx.x;
    int c = idx >> 8, k = idx & 255;
    int hh = c >> 5, kv = c & 31;
    float v = w[hh*256*32 + k*32 + kv];
    __nv_bfloat16 hb = __float2bfloat16(v);
    oh[idx] = hb; ol[idx] = __float2bfloat16(v - __bfloat162float(hb));
}

// ---------------------------------------------------------------------------
// Global softmax stats + fused P materialization (no mask).
// One block per (h,row). Writes P bf16 hi/lo planes [row][Nk].
// ---------------------------------------------------------------------------
__global__ void stats_global_f(const float* __restrict__ m, const float* __restrict__ r,
                               __nv_bfloat16* __restrict__ phi, __nv_bfloat16* __restrict__ pli,
                               int Nq, int Nk){
    extern __shared__ float sbuf[];
    __shared__ float red[256];
    int tid = threadIdx.x;
    int row = blockIdx.x;
    int h = row / Nq;
    float scale = scale_from_r(r[h]);
    const float* mr = m + (size_t)row * Nk;
    float lmin = 3.402823466e38f;
    for (int i = tid; i < Nk; i += 256){
        float sd = mr[i] * scale; sbuf[i] = sd; lmin = fminf(lmin, sd);
    }
    red[tid] = lmin; __syncthreads();
    for (int s=128; s>0; s>>=1){
        if (tid < s) red[tid] = fminf(red[tid], red[tid+s]);
        __syncthreads();
    }
    float mn = red[0]; __syncthreads();
    float ls = 0.f;
    for (int i = tid; i < Nk; i += 256) ls += __expf(mn - sbuf[i]);
    red[tid] = ls; __syncthreads();
    for (int s=128; s>0; s>>=1){
        if (tid < s) red[tid] += red[tid+s];
        __syncthreads();
    }
    float inv = 1.0f / red[0];

    int chunk = Nk >> 8;                      // elems per thread (contiguous)
    size_t base = (size_t)row * Nk + tid*chunk;
    for (int i = 0; i < chunk; i += 2){
        float p0 = __expf(mn - sbuf[tid*chunk + i    ]) * inv;
        float p1 = __expf(mn - sbuf[tid*chunk + i + 1]) * inv;
        uint32_t uh, ul; split_pack(p0, p1, uh, ul);
        *(uint32_t*)(phi + base + i) = uh;
        *(uint32_t*)(pli + base + i) = ul;
    }
}

// ---------------------------------------------------------------------------
// Local softmax stats (30th percentile mask) + fused P materialization.
// Radix-select replaces bitonic sort: exact s[306], s[307] order statistics.
// ---------------------------------------------------------------------------
__global__ void stats_local_f(const float* __restrict__ m, const float* __restrict__ r,
                              __nv_bfloat16* __restrict__ phi, __nv_bfloat16* __restrict__ pli,
                              int Nq){
    __shared__ float    sv[1024];
    __shared__ uint32_t su[1024];
    __shared__ uint32_t hist[256];
    __shared__ float    redf[256];
    __shared__ uint32_t s_sel[2];
    int tid = threadIdx.x;
    int row = blockIdx.x;
    int h = row / Nq;
    float scale = scale_from_r(r[h]);
    const float* mr = m + (size_t)row * 1024;
    float lmin = 3.402823466e38f;
    for (int i = tid; i < 1024; i += 256){
        float sd = mr[i] * scale;
        sv[i] = sd;
        uint32_t b = __float_as_uint(sd);
        su[i] = (b & 0x80000000u) ? ~b : (b | 0x80000000u);   // ascending key
        lmin = fminf(lmin, sd);
    }
    redf[tid] = lmin; __syncthreads();
    for (int s=128; s>0; s>>=1){
        if (tid < s) redf[tid] = fminf(redf[tid], redf[tid+s]);
        __syncthreads();
    }
    float mn = redf[0];

    // radix-select key of rank 306 (0-indexed)
    uint32_t pmask = 0, pval = 0; int kk = 306;
    #pragma unroll
    for (int round = 3; round >= 0; round--){
        int sh = round * 8;
        hist[tid] = 0; __syncthreads();
        for (int i = tid; i < 1024; i += 256){
            uint32_t u = su[i];
            if ((u & pmask) == pval) atomicAdd(&hist[(u >> sh) & 0xFF], 1u);
        }
        __syncthreads();
        for (int off = 1; off < 256; off <<= 1){
            uint32_t v = (tid >= off) ? hist[tid - off] : 0u;
            __syncthreads();
            hist[tid] += v;
            __syncthreads();
        }
        uint32_t incl = hist[tid];
        uint32_t excl = (tid > 0) ? hist[tid-1] : 0u;
        if ((uint32_t)kk >= excl && (uint32_t)kk < incl){
            s_sel[0] = (uint32_t)tid; s_sel[1] = excl;
        }
        __syncthreads();
        uint32_t b = s_sel[0]; kk -= (int)s_sel[1];
        pval  |= (b << sh);
        pmask |= (0xFFu << sh);
        __syncthreads();
    }
    uint32_t k306 = pval;

    // count (<= k306) and min key strictly greater
    uint32_t cle = 0, mg = 0xFFFFFFFFu;
    for (int i = tid; i < 1024; i += 256){
        uint32_t u = su[i];
        if (u <= k306) cle++;
        else if (u < mg) mg = u;
    }
    __syncthreads();                 // all su reads done before scratch reuse
    hist[tid] = cle; su[tid] = mg;
    __syncthreads();
    for (int s=128; s>0; s>>=1){
        if (tid < s){
            hist[tid] += hist[tid+s];
            if (su[tid+s] < su[tid]) su[tid] = su[tid+s];
        }
        __syncthreads();
    }
    uint32_t cle_t = hist[0], mgk = su[0];
    float v306 = key_to_f(k306);
    float v307 = (cle_t >= 308u) ? v306 : key_to_f(mgk);
    float pos = 1023.0f * 0.30f;
    int lo = (int)pos;
    float fr = pos - (float)lo;
    float th = v306 + fr * (v307 - v306);
    __syncthreads();

    // masked denominator
    float ls = 0.f;
    for (int i = tid; i < 1024; i += 256){
        float v = sv[i];
        if (v <= th) ls += __expf(mn - v);
    }
    redf[tid] = ls; __syncthreads();
    for (int s=128; s>0; s>>=1){
        if (tid < s) redf[tid] += redf[tid+s];
        __syncthreads();
    }
    float inv = 1.0f / redf[0];

    // write P (4 contiguous elems per thread)
    size_t base = (size_t)row * 1024 + tid*4;
    float q[4];
    #pragma unroll
    for (int i = 0; i < 4; i++){
        float v = sv[tid*4 + i];
        q[i] = (v <= th) ? __expf(mn - v) * inv : 0.f;
    }
    uint32_t uh0, ul0, uh1, ul1;
    split_pack(q[0], q[1], uh0, ul0);
    split_pack(q[2], q[3], uh1, ul1);
    *(uint32_t*)(phi + base)     = uh0;  *(uint32_t*)(phi + base + 2) = uh1;
    *(uint32_t*)(pli + base)     = ul0;  *(uint32_t*)(pli + base + 2) = ul1;
}

// ---------------------------------------------------------------------------
// Unified WMMA bf16 hi/lo-split GEMM (3-term).  Tile 128x128, K chunks 32,
// cp.async double-buffered.  8 warps = 4(M) x 2(N); warp tile 32x64.
// A = pre-split bf16 planes, row stride lda; A row block = h*MhA + m0.
// EMODE 0: +bias -> f32            1: +bias,gelu -> split planes
//       2: +bias,gelu -> f32       3: +bias+addin,gelu -> split planes
//       4: transpose -> V[h][(b,kv)][n] split planes
//       5: gelu -> split planes scattered to [(b,row)][h*32+k]
// ---------------------------------------------------------------------------
#define ASTRIDE 40
#define PLANEB  (128*ASTRIDE*2)        // 10240 bytes per plane
#define STAGEB  (4*PLANEB)             // 40960 bytes per stage
#define SMEMSZ  (2*STAGEB)             // 81920

template<int EMODE>
__global__ __launch_bounds__(256)
void wmma_gemm(const __nv_bfloat16* __restrict__ Ah, const __nv_bfloat16* __restrict__ Al,
               int lda, int MhA,
               const __nv_bfloat16* __restrict__ Bh, const __nv_bfloat16* __restrict__ Bl,
               int K,
               const float* __restrict__ bias, const float* __restrict__ addin,
               float* __restrict__ outf, __nv_bfloat16* __restrict__ outh,
               __nv_bfloat16* __restrict__ outl, int nper)
{
    extern __shared__ char sm[];
    int tid = threadIdx.x;
    int m0 = blockIdx.x * 128, yb = blockIdx.y * 128, h = blockIdx.z;

    const __nv_bfloat16* pa_h = Ah + ((size_t)h*MhA + m0) * lda;
    const __nv_bfloat16* pa_l = Al + ((size_t)h*MhA + m0) * lda;
    const __nv_bfloat16* pb_h = Bh + (size_t)(h*256 + yb) * K;
    const __nv_bfloat16* pb_l = Bl + (size_t)(h*256 + yb) * K;

    int row  = tid >> 1;
    int half = tid & 1;

    auto produce = [&](int c, int s){
        char* base = sm + s*STAGEB;
        int n0 = c*32;
        uint32_t sA = smem_u32(base) + (uint32_t)(row*(ASTRIDE*2) + half*32);
        const __nv_bfloat16* ah = pa_h + (size_t)row*lda + n0 + half*16;
        const __nv_bfloat16* al = pa_l + (size_t)row*lda + n0 + half*16;
        CP_ASYNC16(sA,                ah);
        CP_ASYNC16(sA + 16,           ah + 8);
        CP_ASYNC16(sA + PLANEB,      al);
        CP_ASYNC16(sA + PLANEB + 16, al + 8);
        const __nv_bfloat16* bh = pb_h + (size_t)row*K + n0 + half*16;
        const __nv_bfloat16* bl = pb_l + (size_t)row*K + n0 + half*16;
        uint32_t sB = sA + 2*PLANEB;
        CP_ASYNC16(sB,               bh);
        CP_ASYNC16(sB + 16,          bh + 8);
        CP_ASYNC16(sB + PLANEB,      bl);
        CP_ASYNC16(sB + PLANEB + 16, bl + 8);
    };

    int wid = tid >> 5;
    int wm = wid >> 1, wn = wid & 1;

    wmma::fragment<wmma::accumulator, 16,16,16, float> acc[2][4];
    #pragma unroll
    for (int im=0;im<2;im++)
        #pragma unroll
        for (int in=0;in<4;in++) wmma::fill_fragment(acc[im][in], 0.0f);

    int nch = K >> 5;
    produce(0, 0);
    CP_COMMIT();

    for (int c = 0; c < nch; c++){
        if (c + 1 < nch){ produce(c+1, (c+1)&1); CP_COMMIT(); CP_WAIT(1); }
        else            { CP_WAIT(0); }
        __syncthreads();

        const char* base = sm + (c&1)*STAGEB;
        const __nv_bfloat16* As_h = (const __nv_bfloat16*)(base);
        const __nv_bfloat16* As_l = (const __nv_bfloat16*)(base + PLANEB);
        const __nv_bfloat16* Bs_h = (const __nv_bfloat16*)(base + 2*PLANEB);
        const __nv_bfloat16* Bs_l = (const __nv_bfloat16*)(base + 3*PLANEB);

        #pragma unroll
        for (int kk = 0; kk < 32; kk += 16){
            wmma::fragment<wmma::matrix_a, 16,16,16, __nv_bfloat16, wmma::row_major> ah[2], al[2];
            #pragma unroll
            for (int im=0;im<2;im++){
                wmma::load_matrix_sync(ah[im], As_h + (wm*32 + im*16)*ASTRIDE + kk, ASTRIDE);
                wmma::load_matrix_sync(al[im], As_l + (wm*32 + im*16)*ASTRIDE + kk, ASTRIDE);
            }
            #pragma unroll
            for (int in=0;in<4;in++){
                int n0 = wn*64 + in*16;
                wmma::fragment<wmma::matrix_b, 16,16,16, __nv_bfloat16, wmma::col_major> bh, bl;
                wmma::load_matrix_sync(bh, Bs_h + n0*ASTRIDE + kk, ASTRIDE);
                wmma::load_matrix_sync(bl, Bs_l + n0*ASTRIDE + kk, ASTRIDE);
                #pragma unroll
                for (int im=0;im<2;im++){
                    wmma::mma_sync(acc[im][in], ah[im], bh, acc[im][in]);
                    wmma::mma_sync(acc[im][in], ah[im], bl, acc[im][in]);
                    wmma::mma_sync(acc[im][in], al[im], bh, acc[im][in]);
                }
            }
        }
        __syncthreads();
    }

    // Epilogue: dump fp32 tile to smem, post-process
    float* Sf = (float*)sm;                      // 128 x 136
    #pragma unroll
    for (int im=0;im<2;im++)
        #pragma unroll
        for (int in=0;in<4;in++)
            wmma::store_matrix_sync(Sf + (wm*32 + im*16)*136 + wn*64 + in*16,
                                    acc[im][in], 136, wmma::mem_row_major);
    __syncthreads();

    if (EMODE == 4){
        int j = tid >> 1, mh = tid & 1;
        int cg = yb + j;
        int bidx = m0 / nper;
        size_t rowo = ((size_t)(cg>>5)*256 + bidx*32 + (cg&31)) * (size_t)nper
                    + (size_t)(m0 - bidx*nper) + mh*64;
        #pragma unroll
        for (int i=0;i<64;i+=2){
            float v0 = Sf[(mh*64+i  )*136 + j];
            float v1 = Sf[(mh*64+i+1)*136 + j];
            uint32_t uh, ul; split_pack(v0, v1, uh, ul);
            *(uint32_t*)(outh + rowo + i) = uh;
            *(uint32_t*)(outl + rowo + i) = ul;
        }
    } else {
        int mm = tid >> 1, ch0 = (tid & 1)*64;
        #pragma unroll
        for (int j=0;j<64;j+=2){
            int c1 = ch0 + j;
            int gc = yb + c1;
            float v0 = Sf[mm*136 + c1], v1 = Sf[mm*136 + c1 + 1];
            if (EMODE==0||EMODE==1||EMODE==2||EMODE==3){
                v0 += bias[gc]; v1 += bias[gc+1];
            }
            size_t ob;
            if (EMODE == 5){
                int b = gc >> 5, k = gc & 31;
                ob = ((size_t)b*nper + m0 + mm)*256 + (size_t)h*32 + k;
            } else {
                ob = (size_t)(m0 + mm)*256 + gc;
            }
            if (EMODE==3){ v0 += addin[ob]; v1 += addin[ob+1]; }
            if (EMODE==1||EMODE==2||EMODE==3||EMODE==5){ v0 = gelu_f(v0); v1 = gelu_f(v1); }
            if (EMODE==0||EMODE==2){
                outf[ob] = v0; outf[ob+1] = v1;
            } else {
                uint32_t uh, ul; split_pack(v0, v1, uh, ul);
                *(uint32_t*)(outh + ob) = uh;
                *(uint32_t*)(outl + ob) = ul;
            }
        }
    }
}

// ---------------------------------------------------------------------------
// Final dense 256 -> 1
// ---------------------------------------------------------------------------
__global__ void final_dense_kernel(const float* __restrict__ hin,
                                   const float* __restrict__ w,
                                   const float* __restrict__ bias,
                                   float* __restrict__ out){
    int warp = threadIdx.x >> 5, lane = threadIdx.x & 31;
    int row = blockIdx.x * 8 + warp;
    const float* hr = hin + (size_t)row * 256;
    float s = 0.f;
    #pragma unroll
    for (int i = 0; i < 8; i++) s += hr[lane + 32*i] * w[lane + 32*i];
    #pragma unroll
    for (int off = 16; off; off >>= 1) s += __shfl_xor_sync(0xffffffff, s, off);
    if (lane == 0) out[row] = s + bias[0];
}

// ---------------------------------------------------------------------------
// Host orchestration
// ---------------------------------------------------------------------------
extern "C" void kernel_launch(void* const* d_in, const int* in_sizes, int n_in,
                              void* d_out, int out_size){
    const float* x      = (const float*)d_in[0];
    const float* m_down = (const float*)d_in[1];
    const float* m_p[2] = {(const float*)d_in[2], (const float*)d_in[3]};
    const float* m_up   = (const float*)d_in[4];
    const float* en_w   = (const float*)d_in[5];
    const float* en_b   = (const float*)d_in[6];
    const float* down_r = (const float*)d_in[7];
    const float* down_w = (const float*)d_in[8];
    const float* pa_r[2]= {(const float*)d_in[9],  (const float*)d_in[17]};
    const float* pa_w[2]= {(const float*)d_in[10], (const float*)d_in[18]};
    const float* f1w[2] = {(const float*)d_in[11], (const float*)d_in[19]};
    const float* f1b[2] = {(const float*)d_in[12], (const float*)d_in[20]};
    const float* f2w[2] = {(const float*)d_in[13], (const float*)d_in[21]};
    const float* f2b[2] = {(const float*)d_in[14], (const float*)d_in[22]};
    const float* rw[2]  = {(const float*)d_in[15], (const float*)d_in[23]};
    const float* rb[2]  = {(const float*)d_in[16], (const float*)d_in[24]};
    const float* up_r   = (const float*)d_in[25];
    const float* up_w   = (const float*)d_in[26];
    const float* de1w   = (const float*)d_in[27];
    const float* de1b   = (const float*)d_in[28];
    const float* de2w   = (const float*)d_in[29];
    const float* de2b   = (const float*)d_in[30];
    float* outp = (float*)d_out;

    __nv_bfloat16 *b0h,*b0l,*lath,*latl,*pah,*pal,*t1h,*t1l,*vh,*vl,*wh,*wl,*phi,*pli;
    float *b1,*t3;
    cudaGetSymbolAddress((void**)&b0h, g_b0h);  cudaGetSymbolAddress((void**)&b0l, g_b0l);
    cudaGetSymbolAddress((void**)&b1,  g_b1);
    cudaGetSymbolAddress((void**)&lath,g_lath); cudaGetSymbolAddress((void**)&latl,g_latl);
    cudaGetSymbolAddress((void**)&pah, g_pah);  cudaGetSymbolAddress((void**)&pal, g_pal);
    cudaGetSymbolAddress((void**)&t1h, g_t1h);  cudaGetSymbolAddress((void**)&t1l, g_t1l);
    cudaGetSymbolAddress((void**)&t3,  g_t3);
    cudaGetSymbolAddress((void**)&vh,  g_vh);   cudaGetSymbolAddress((void**)&vl,  g_vl);
    cudaGetSymbolAddress((void**)&wh,  g_wh);   cudaGetSymbolAddress((void**)&wl,  g_wl);
    cudaGetSymbolAddress((void**)&phi, g_ph);   cudaGetSymbolAddress((void**)&pli, g_pl);

    cudaFuncSetAttribute((const void*)wmma_gemm<4>, cudaFuncAttributeMaxDynamicSharedMemorySize, SMEMSZ);
    cudaFuncSetAttribute((const void*)wmma_gemm<5>, cudaFuncAttributeMaxDynamicSharedMemorySize, SMEMSZ);
    cudaFuncSetAttribute((const void*)wmma_gemm<1>, cudaFuncAttributeMaxDynamicSharedMemorySize, SMEMSZ);
    cudaFuncSetAttribute((const void*)wmma_gemm<0>, cudaFuncAttributeMaxDynamicSharedMemorySize, SMEMSZ);
    cudaFuncSetAttribute((const void*)wmma_gemm<3>, cudaFuncAttributeMaxDynamicSharedMemorySize, SMEMSZ);
    cudaFuncSetAttribute((const void*)wmma_gemm<2>, cudaFuncAttributeMaxDynamicSharedMemorySize, SMEMSZ);

    // 1. encoder -> b0 hi/lo planes
    encoder_kernel<<<MBIG, 256>>>(x, en_w, en_b, b0h, b0l);

    // 2. down pos_att (global)
    split_attn_w<<<256, 256>>>(down_w, wh, wl);
    wmma_gemm<4><<<dim3(MBIG/128,2,1), 256, SMEMSZ>>>(
        b0h, b0l, 256, 0, wh, wl, 256, nullptr, nullptr, nullptr, vh, vl, NFULL);
    stats_global_f<<<HEADS*NLAT, 256, NFULL*4>>>(m_down, down_r, phi, pli, NLAT, NFULL);
    wmma_gemm<5><<<dim3(NLAT/128,2,HEADS), 256, SMEMSZ>>>(
        phi, pli, NFULL, NLAT, vh, vl, NFULL, nullptr, nullptr, nullptr, lath, latl, NLAT);

    // 3. latent blocks (local, 30th percentile)
    for (int blk = 0; blk < 2; blk++){
        stats_local_f<<<HEADS*NLAT, 256>>>(m_p[blk], pa_r[blk], phi, pli, NLAT);
        split_attn_w<<<256, 256>>>(pa_w[blk], wh, wl);
        wmma_gemm<4><<<dim3(MLAT/128,2,1), 256, SMEMSZ>>>(
            lath, latl, 256, 0, wh, wl, 256, nullptr, nullptr, nullptr, vh, vl, NLAT);
        wmma_gemm<5><<<dim3(NLAT/128,2,HEADS), 256, SMEMSZ>>>(
            phi, pli, NLAT, NLAT, vh, vl, NLAT, nullptr, nullptr, nullptr, pah, pal, NLAT);
        split_dense_w<<<256, 256>>>(f1w[blk], wh, wl);
        wmma_gemm<1><<<dim3(MLAT/128,2,1), 256, SMEMSZ>>>(
            pah, pal, 256, 0, wh, wl, 256, f1b[blk], nullptr, nullptr, t1h, t1l, 0);
        split_dense_w<<<256, 256>>>(rw[blk], wh, wl);
        wmma_gemm<0><<<dim3(MLAT/128,2,1), 256, SMEMSZ>>>(
            lath, latl, 256, 0, wh, wl, 256, rb[blk], nullptr, t3, nullptr, nullptr, 0);
        split_dense_w<<<256, 256>>>(f2w[blk], wh, wl);
        wmma_gemm<3><<<dim3(MLAT/128,2,1), 256, SMEMSZ>>>(
            t1h, t1l, 256, 0, wh, wl, 256, f2b[blk], t3, nullptr, lath, latl, 0);
    }

    // 4. up pos_att (global)
    stats_global_f<<<HEADS*NFULL, 256, NLAT*4>>>(m_up, up_r, phi, pli, NFULL, NLAT);
    split_attn_w<<<256, 256>>>(up_w, wh, wl);
    wmma_gemm<4><<<dim3(MLAT/128,2,1), 256, SMEMSZ>>>(
        lath, latl, 256, 0, wh, wl, 256, nullptr, nullptr, nullptr, vh, vl, NLAT);
    wmma_gemm<5><<<dim3(NFULL/128,2,HEADS), 256, SMEMSZ>>>(
        phi, pli, NLAT, NFULL, vh, vl, NLAT, nullptr, nullptr, nullptr, b0h, b0l, NFULL);

    // 5. decoder
    split_dense_w<<<256, 256>>>(de1w, wh, wl);
    wmma_gemm<2><<<dim3(MBIG/128,2,1), 256, SMEMSZ>>>(
        b0h, b0l, 256, 0, wh, wl, 256, de1b, nullptr, b1, nullptr, nullptr, 0);
    final_dense_kernel<<<MBIG/8, 256>>>(b1, de2w, de2b, outp);
}

// round 16
// speedup vs baseline: 2.9422x; 1.1096x over previous
#include <cuda_runtime.h>
#include <cuda_bf16.h>
#include <mma.h>
#include <math.h>
#include <stdint.h>

using namespace nvcuda;

#define Bq      8
#define NFULL   4096
#define NLAT    1024
#define HEADS   8
#define MBIG    (Bq*NFULL)   // 32768
#define MLAT    (Bq*NLAT)    // 8192

// ---------------------------------------------------------------------------
// Scratch (device globals; no allocation allowed)
// ---------------------------------------------------------------------------
__device__ __nv_bfloat16 g_b0h[MBIG*256], g_b0l[MBIG*256];
__device__ float         g_b1[MBIG*256];
__device__ __nv_bfloat16 g_lath[MLAT*256], g_latl[MLAT*256];
__device__ __nv_bfloat16 g_pah[MLAT*256],  g_pal[MLAT*256];
__device__ __nv_bfloat16 g_t1h[MLAT*256],  g_t1l[MLAT*256];
__device__ float         g_t3[MLAT*256];
__device__ __nv_bfloat16 g_vh[HEADS*256*NFULL], g_vl[HEADS*256*NFULL];
__device__ __nv_bfloat16 g_wh[256*256], g_wl[256*256];
__device__ __nv_bfloat16 g_ph[HEADS*NFULL*NLAT], g_pl[HEADS*NFULL*NLAT];  // P planes
__device__ float g_pk[4*HEADS*NLAT*256];   // split-K partials (32 MB)

// ---------------------------------------------------------------------------
// Helpers
// ---------------------------------------------------------------------------
__device__ __forceinline__ uint32_t smem_u32(const void* p){
    uint32_t a;
    asm("{ .reg .u64 t; cvta.to.shared.u64 t, %1; cvt.u32.u64 %0, t; }" : "=r"(a) : "l"(p));
    return a;
}
#define CP_ASYNC16(dst, src) \
    asm volatile("cp.async.ca.shared.global [%0], [%1], 16;" :: "r"(dst), "l"(src))
#define CP_COMMIT() asm volatile("cp.async.commit_group;" ::: "memory")
#define CP_WAIT(N)  asm volatile("cp.async.wait_group %0;" :: "n"(N) : "memory")

__device__ __forceinline__ void split_pack(float v0, float v1, uint32_t& h, uint32_t& l){
    float h0 = __bfloat162float(__float2bfloat16(v0));
    float h1 = __bfloat162float(__float2bfloat16(v1));
    __nv_bfloat162 hh = __floats2bfloat162_rn(v0, v1);
    __nv_bfloat162 ll = __floats2bfloat162_rn(v0 - h0, v1 - h1);
    h = reinterpret_cast<uint32_t&>(hh);
    l = reinterpret_cast<uint32_t&>(ll);
}
__device__ __forceinline__ float gelu_f(float v){
    float t = tanhf(0.7978845608028654f * (v + 0.044715f * v * v * v));
    return 0.5f * v * (1.0f + t);
}
__device__ __forceinline__ float scale_from_r(float r){
    const float A = 0.7853980848576320f;
    return tanf(A * (1.0f + sinf(r)));
}
__device__ __forceinline__ float key_to_f(uint32_t u){
    uint32_t b = (u & 0x80000000u) ? (u & 0x7FFFFFFFu) : ~u;
    return __uint_as_float(b);
}

// ---------------------------------------------------------------------------
// Encoder: gelu(x @ W[4,256] + b) -> bf16 hi/lo planes
// ---------------------------------------------------------------------------
__global__ void encoder_kernel(const float* __restrict__ x,
                               const float* __restrict__ W,
                               const float* __restrict__ bias,
                               __nv_bfloat16* __restrict__ oh,
                               __nv_bfloat16* __restrict__ ol){
    int m = blockIdx.x, c = threadIdx.x;
    const float* xr = x + (size_t)m * 4;
    float v = bias[c] + xr[0]*W[c] + xr[1]*W[256+c] + xr[2]*W[512+c] + xr[3]*W[768+c];
    v = gelu_f(v);
    __nv_bfloat16 hb = __float2bfloat16(v);
    oh[(size_t)m*256 + c] = hb;
    ol[(size_t)m*256 + c] = __float2bfloat16(v - __bfloat162float(hb));
}

// ---------------------------------------------------------------------------
// Weight split kernels: output B-layout [n][k]
// ---------------------------------------------------------------------------
__global__ void split_dense_w(const float* __restrict__ W,
                              __nv_bfloat16* __restrict__ oh, __nv_bfloat16* __restrict__ ol){
    int idx = blockIdx.x*256 + threadIdx.x;
    int c = idx >> 8, k = idx & 255;
    float v = W[k*256 + c];
    __nv_bfloat16 hb = __float2bfloat16(v);
    oh[idx] = hb; ol[idx] = __float2bfloat16(v - __bfloat162float(hb));
}
__global__ void split_attn_w(const float* __restrict__ w,
                             __nv_bfloat16* __restrict__ oh, __nv_bfloat16* __restrict__ ol){
    int idx = blockIdx.x*256 + threadIdx.x;
    int c = idx >> 8, k = idx & 255;
    int hh = c >> 5, kv = c & 31;
    float v = w[hh*256*32 + k*32 + kv];
    __nv_bfloat16 hb = __float2bfloat16(v);
    oh[idx] = hb; ol[idx] = __float2bfloat16(v - __bfloat162float(hb));
}

// ---------------------------------------------------------------------------
// Global softmax stats + fused P write, register-resident.
// Each thread owns NK/256 consecutive-pair elements (float2).
// ---------------------------------------------------------------------------
template<int NK>
__global__ __launch_bounds__(256)
void stats_global_f(const float* __restrict__ m, const float* __restrict__ r,
                    __nv_bfloat16* __restrict__ phi, __nv_bfloat16* __restrict__ pli,
                    int Nq){
    constexpr int NIT = NK/512;
    __shared__ float sred[16];
    int tid = threadIdx.x, lane = tid & 31, wid = tid >> 5;
    int row = blockIdx.x, h = row / Nq;
    float scale = scale_from_r(r[h]);
    const float2* mr = (const float2*)(m + (size_t)row * NK);
    float2 v[NIT];
    float lmin = 3.402823466e38f;
    #pragma unroll
    for (int i = 0; i < NIT; i++){
        v[i] = mr[tid + 256*i];
        v[i].x *= scale; v[i].y *= scale;
        lmin = fminf(lmin, fminf(v[i].x, v[i].y));
    }
    #pragma unroll
    for (int o = 16; o; o >>= 1) lmin = fminf(lmin, __shfl_xor_sync(0xffffffffu, lmin, o));
    if (lane == 0) sred[wid] = lmin;
    __syncthreads();
    float mn = sred[0];
    #pragma unroll
    for (int w = 1; w < 8; w++) mn = fminf(mn, sred[w]);

    float ls = 0.f;
    #pragma unroll
    for (int i = 0; i < NIT; i++){
        float e0 = __expf(mn - v[i].x), e1 = __expf(mn - v[i].y);
        v[i].x = e0; v[i].y = e1;
        ls += e0 + e1;
    }
    #pragma unroll
    for (int o = 16; o; o >>= 1) ls += __shfl_xor_sync(0xffffffffu, ls, o);
    if (lane == 0) sred[8 + wid] = ls;
    __syncthreads();
    float tot = sred[8];
    #pragma unroll
    for (int w = 1; w < 8; w++) tot += sred[8 + w];
    float inv = 1.0f / tot;

    uint32_t* ph = (uint32_t*)(phi + (size_t)row * NK);
    uint32_t* pl = (uint32_t*)(pli + (size_t)row * NK);
    #pragma unroll
    for (int i = 0; i < NIT; i++){
        uint32_t uh, ul;
        split_pack(v[i].x * inv, v[i].y * inv, uh, ul);
        ph[tid + 256*i] = uh;
        pl[tid + 256*i] = ul;
    }
}

// ---------------------------------------------------------------------------
// Local softmax stats (30th percentile) + fused P write, register-resident.
// NK = 1024: 4 elems/thread in registers; radix-select from registers.
// ---------------------------------------------------------------------------
__global__ __launch_bounds__(256)
void stats_local_f(const float* __restrict__ m, const float* __restrict__ r,
                   __nv_bfloat16* __restrict__ phi, __nv_bfloat16* __restrict__ pli,
                   int Nq){
    __shared__ uint32_t hist[256];
    __shared__ float    sred[16];
    __shared__ uint32_t sredu[16];
    __shared__ uint32_t s_sel[2];
    int tid = threadIdx.x, lane = tid & 31, wid = tid >> 5;
    int row = blockIdx.x, h = row / Nq;
    float scale = scale_from_r(r[h]);
    const float2* mr = (const float2*)(m + (size_t)row * 1024);
    float2 v[2];
    uint32_t ky[4];
    float lmin = 3.402823466e38f;
    #pragma unroll
    for (int i = 0; i < 2; i++){
        v[i] = mr[tid + 256*i];
        v[i].x *= scale; v[i].y *= scale;
        lmin = fminf(lmin, fminf(v[i].x, v[i].y));
        uint32_t b0 = __float_as_uint(v[i].x);
        uint32_t b1 = __float_as_uint(v[i].y);
        ky[2*i]   = (b0 & 0x80000000u) ? ~b0 : (b0 | 0x80000000u);
        ky[2*i+1] = (b1 & 0x80000000u) ? ~b1 : (b1 | 0x80000000u);
    }
    #pragma unroll
    for (int o = 16; o; o >>= 1) lmin = fminf(lmin, __shfl_xor_sync(0xffffffffu, lmin, o));
    if (lane == 0) sred[wid] = lmin;
    __syncthreads();
    float mn = sred[0];
    #pragma unroll
    for (int w = 1; w < 8; w++) mn = fminf(mn, sred[w]);

    // radix-select rank 306 (0-indexed) over keys
    uint32_t pmask = 0, pval = 0; int kk = 306;
    #pragma unroll
    for (int round = 3; round >= 0; round--){
        int sh = round * 8;
        hist[tid] = 0; __syncthreads();
        #pragma unroll
        for (int j = 0; j < 4; j++){
            uint32_t u = ky[j];
            if ((u & pmask) == pval) atomicAdd(&hist[(u >> sh) & 0xFF], 1u);
        }
        __syncthreads();
        for (int off = 1; off < 256; off <<= 1){
            uint32_t t = (tid >= off) ? hist[tid - off] : 0u;
            __syncthreads();
            hist[tid] += t;
            __syncthreads();
        }
        uint32_t incl = hist[tid];
        uint32_t excl = (tid > 0) ? hist[tid-1] : 0u;
        if ((uint32_t)kk >= excl && (uint32_t)kk < incl){
            s_sel[0] = (uint32_t)tid; s_sel[1] = excl;
        }
        __syncthreads();
        uint32_t b = s_sel[0]; kk -= (int)s_sel[1];
        pval  |= (b << sh);
        pmask |= (0xFFu << sh);
        __syncthreads();
    }
    uint32_t k306 = pval;

    // count <= k306 and min strictly-greater key
    uint32_t cle = 0, mg = 0xFFFFFFFFu;
    #pragma unroll
    for (int j = 0; j < 4; j++){
        uint32_t u = ky[j];
        if (u <= k306) cle++;
        else if (u < mg) mg = u;
    }
    #pragma unroll
    for (int o = 16; o; o >>= 1){
        cle += __shfl_xor_sync(0xffffffffu, cle, o);
        uint32_t om = __shfl_xor_sync(0xffffffffu, mg, o);
        if (om < mg) mg = om;
    }
    if (lane == 0){ hist[wid] = cle; sredu[wid] = mg; }
    __syncthreads();
    uint32_t cle_t = hist[0], mgk = sredu[0];
    #pragma unroll
    for (int w = 1; w < 8; w++){
        cle_t += hist[w];
        if (sredu[w] < mgk) mgk = sredu[w];
    }
    float v306 = key_to_f(k306);
    float v307 = (cle_t >= 308u) ? v306 : key_to_f(mgk);
    float pos = 1023.0f * 0.30f;
    int lo = (int)pos;
    float fr = pos - (float)lo;
    float th = v306 + fr * (v307 - v306);

    // masked exp + denominator (exp kept in registers)
    float ls = 0.f;
    #pragma unroll
    for (int i = 0; i < 2; i++){
        float e0 = (v[i].x <= th) ? __expf(mn - v[i].x) : 0.f;
        float e1 = (v[i].y <= th) ? __expf(mn - v[i].y) : 0.f;
        v[i].x = e0; v[i].y = e1;
        ls += e0 + e1;
    }
    #pragma unroll
    for (int o = 16; o; o >>= 1) ls += __shfl_xor_sync(0xffffffffu, ls, o);
    if (lane == 0) sred[8 + wid] = ls;
    __syncthreads();
    float tot = sred[8];
    #pragma unroll
    for (int w = 1; w < 8; w++) tot += sred[8 + w];
    float inv = 1.0f / tot;

    uint32_t* ph = (uint32_t*)(phi + (size_t)row * 1024);
    uint32_t* pl = (uint32_t*)(pli + (size_t)row * 1024);
    #pragma unroll
    for (int i = 0; i < 2; i++){
        uint32_t uh, ul;
        split_pack(v[i].x * inv, v[i].y * inv, uh, ul);
        ph[tid + 256*i] = uh;
        pl[tid + 256*i] = ul;
    }
}

// ---------------------------------------------------------------------------
// Unified WMMA bf16 hi/lo-split GEMM (3-term).  Tile 128x128, K chunks 32,
// cp.async double-buffered.  8 warps = 4(M) x 2(N); warp tile 32x64.
// A = pre-split bf16 planes, row stride lda; A row block = h*MhA + m0.
// EMODE 0: +bias -> f32            1: +bias,gelu -> split planes
//       2: +bias,gelu -> f32       3: +bias+addin,gelu -> split planes
//       4: transpose -> V[h][(b,kv)][n] split planes
//       5: gelu -> split planes scattered to [(b,row)][h*32+k]
//       6: split-K raw f32 partials; nper = K-split size; gridDim.z = HEADS*NS
// ---------------------------------------------------------------------------
#define ASTRIDE 40
#define PLANEB  (128*ASTRIDE*2)        // 10240 bytes per plane
#define STAGEB  (4*PLANEB)             // 40960 bytes per stage
#define SMEMSZ  (2*STAGEB)             // 81920

template<int EMODE>
__global__ __launch_bounds__(256)
void wmma_gemm(const __nv_bfloat16* __restrict__ Ah, const __nv_bfloat16* __restrict__ Al,
               int lda, int MhA,
               const __nv_bfloat16* __restrict__ Bh, const __nv_bfloat16* __restrict__ Bl,
               int K,
               const float* __restrict__ bias, const float* __restrict__ addin,
               float* __restrict__ outf, __nv_bfloat16* __restrict__ outh,
               __nv_bfloat16* __restrict__ outl, int nper)
{
    extern __shared__ char sm[];
    int tid = threadIdx.x;
    int m0 = blockIdx.x * 128, yb = blockIdx.y * 128;
    int h  = blockIdx.z % HEADS;
    int sk = blockIdx.z / HEADS;                  // split index (EMODE6), else 0
    int KS = (EMODE == 6) ? nper : K;
    int Koff = sk * KS;

    const __nv_bfloat16* pa_h = Ah + ((size_t)h*MhA + m0) * lda + Koff;
    const __nv_bfloat16* pa_l = Al + ((size_t)h*MhA + m0) * lda + Koff;
    const __nv_bfloat16* pb_h = Bh + (size_t)(h*256 + yb) * K + Koff;
    const __nv_bfloat16* pb_l = Bl + (size_t)(h*256 + yb) * K + Koff;

    int row  = tid >> 1;
    int half = tid & 1;

    auto produce = [&](int c, int s){
        char* base = sm + s*STAGEB;
        int n0 = c*32;
        uint32_t sA = smem_u32(base) + (uint32_t)(row*(ASTRIDE*2) + half*32);
        const __nv_bfloat16* ah = pa_h + (size_t)row*lda + n0 + half*16;
        const __nv_bfloat16* al = pa_l + (size_t)row*lda + n0 + half*16;
        CP_ASYNC16(sA,                ah);
        CP_ASYNC16(sA + 16,           ah + 8);
        CP_ASYNC16(sA + PLANEB,      al);
        CP_ASYNC16(sA + PLANEB + 16, al + 8);
        const __nv_bfloat16* bh = pb_h + (size_t)row*K + n0 + half*16;
        const __nv_bfloat16* bl = pb_l + (size_t)row*K + n0 + half*16;
        uint32_t sB = sA + 2*PLANEB;
        CP_ASYNC16(sB,               bh);
        CP_ASYNC16(sB + 16,          bh + 8);
        CP_ASYNC16(sB + PLANEB,      bl);
        CP_ASYNC16(sB + PLANEB + 16, bl + 8);
    };

    int wid = tid >> 5;
    int wm = wid >> 1, wn = wid & 1;

    wmma::fragment<wmma::accumulator, 16,16,16, float> acc[2][4];
    #pragma unroll
    for (int im=0;im<2;im++)
        #pragma unroll
        for (int in=0;in<4;in++) wmma::fill_fragment(acc[im][in], 0.0f);

    int nch = KS >> 5;
    produce(0, 0);
    CP_COMMIT();

    for (int c = 0; c < nch; c++){
        if (c + 1 < nch){ produce(c+1, (c+1)&1); CP_COMMIT(); CP_WAIT(1); }
        else            { CP_WAIT(0); }
        __syncthreads();

        const char* base = sm + (c&1)*STAGEB;
        const __nv_bfloat16* As_h = (const __nv_bfloat16*)(base);
        const __nv_bfloat16* As_l = (const __nv_bfloat16*)(base + PLANEB);
        const __nv_bfloat16* Bs_h = (const __nv_bfloat16*)(base + 2*PLANEB);
        const __nv_bfloat16* Bs_l = (const __nv_bfloat16*)(base + 3*PLANEB);

        #pragma unroll
        for (int kk = 0; kk < 32; kk += 16){
            wmma::fragment<wmma::matrix_a, 16,16,16, __nv_bfloat16, wmma::row_major> ah[2], al[2];
            #pragma unroll
            for (int im=0;im<2;im++){
                wmma::load_matrix_sync(ah[im], As_h + (wm*32 + im*16)*ASTRIDE + kk, ASTRIDE);
                wmma::load_matrix_sync(al[im], As_l + (wm*32 + im*16)*ASTRIDE + kk, ASTRIDE);
            }
            #pragma unroll
            for (int in=0;in<4;in++){
                int n0 = wn*64 + in*16;
                wmma::fragment<wmma::matrix_b, 16,16,16, __nv_bfloat16, wmma::col_major> bh, bl;
                wmma::load_matrix_sync(bh, Bs_h + n0*ASTRIDE + kk, ASTRIDE);
                wmma::load_matrix_sync(bl, Bs_l + n0*ASTRIDE + kk, ASTRIDE);
                #pragma unroll
                for (int im=0;im<2;im++){
                    wmma::mma_sync(acc[im][in], ah[im], bh, acc[im][in]);
                    wmma::mma_sync(acc[im][in], ah[im], bl, acc[im][in]);
                    wmma::mma_sync(acc[im][in], al[im], bh, acc[im][in]);
                }
            }
        }
        __syncthreads();
    }

    // Epilogue: dump fp32 tile to smem, post-process
    float* Sf = (float*)sm;                      // 128 x 136
    #pragma unroll
    for (int im=0;im<2;im++)
        #pragma unroll
        for (int in=0;in<4;in++)
            wmma::store_matrix_sync(Sf + (wm*32 + im*16)*136 + wn*64 + in*16,
                                    acc[im][in], 136, wmma::mem_row_major);
    __syncthreads();

    if (EMODE == 4){
        int j = tid >> 1, mh = tid & 1;
        int cg = yb + j;
        int bidx = m0 / nper;
        size_t rowo = ((size_t)(cg>>5)*256 + bidx*32 + (cg&31)) * (size_t)nper
                    + (size_t)(m0 - bidx*nper) + mh*64;
        #pragma unroll
        for (int i=0;i<64;i+=2){
            float v0 = Sf[(mh*64+i  )*136 + j];
            float v1 = Sf[(mh*64+i+1)*136 + j];
            uint32_t uh, ul; split_pack(v0, v1, uh, ul);
            *(uint32_t*)(outh + rowo + i) = uh;
            *(uint32_t*)(outl + rowo + i) = ul;
        }
    } else {
        int Mtot = gridDim.x * 128;
        int mm = tid >> 1, ch0 = (tid & 1)*64;
        #pragma unroll
        for (int j=0;j<64;j+=2){
            int c1 = ch0 + j;
            int gc = yb + c1;
            float v0 = Sf[mm*136 + c1], v1 = Sf[mm*136 + c1 + 1];
            if (EMODE==0||EMODE==1||EMODE==2||EMODE==3){
                v0 += bias[gc]; v1 += bias[gc+1];
            }
            size_t ob;
            if (EMODE == 5){
                int b = gc >> 5, k = gc & 31;
                ob = ((size_t)b*nper + m0 + mm)*256 + (size_t)h*32 + k;
            } else if (EMODE == 6){
                ob = ((size_t)(sk*HEADS + h)*Mtot + m0 + mm)*256 + gc;
            } else {
                ob = (size_t)(m0 + mm)*256 + gc;
            }
            if (EMODE==3){ v0 += addin[ob]; v1 += addin[ob+1]; }
            if (EMODE==1||EMODE==2||EMODE==3||EMODE==5){ v0 = gelu_f(v0); v1 = gelu_f(v1); }
            if (EMODE==0||EMODE==2||EMODE==6){
                outf[ob] = v0; outf[ob+1] = v1;
            } else {
                uint32_t uh, ul; split_pack(v0, v1, uh, ul);
                *(uint32_t*)(outh + ob) = uh;
                *(uint32_t*)(outl + ob) = ul;
            }
        }
    }
}

// ---------------------------------------------------------------------------
// Split-K reduce: sum NS partials, gelu, split, scatter to [(b,row)][h*32+k]
// ---------------------------------------------------------------------------
__global__ void apply_reduce(const float* __restrict__ pbuf, int NS, int Mh,
                             __nv_bfloat16* __restrict__ outh,
                             __nv_bfloat16* __restrict__ outl, int nper){
    int idx = blockIdx.x*256 + threadIdx.x;   // pair index over HEADS*Mh*128
    int colp = idx & 127;
    int t = idx >> 7;                          // t = h*Mh + mrow
    int mrow = t % Mh;
    int h = t / Mh;
    size_t base = (size_t)t * 256 + colp*2;
    size_t pstride = (size_t)HEADS * Mh * 256;
    float s0 = 0.f, s1 = 0.f;
    for (int s = 0; s < NS; s++){
        const float* p = pbuf + s*pstride + base;
        s0 += p[0]; s1 += p[1];
    }
    s0 = gelu_f(s0); s1 = gelu_f(s1);
    uint32_t uh, ul; split_pack(s0, s1, uh, ul);
    int gc = colp*2;
    int b = gc >> 5, k = gc & 31;
    size_t ob = ((size_t)b*nper + mrow)*256 + (size_t)h*32 + k;
    *(uint32_t*)(outh + ob) = uh;
    *(uint32_t*)(outl + ob) = ul;
}

// ---------------------------------------------------------------------------
// Final dense 256 -> 1
// ---------------------------------------------------------------------------
__global__ void final_dense_kernel(const float* __restrict__ hin,
                                   const float* __restrict__ w,
                                   const float* __restrict__ bias,
                                   float* __restrict__ out){
    int warp = threadIdx.x >> 5, lane = threadIdx.x & 31;
    int row = blockIdx.x * 8 + warp;
    const float* hr = hin + (size_t)row * 256;
    float s = 0.f;
    #pragma unroll
    for (int i = 0; i < 8; i++) s += hr[lane + 32*i] * w[lane + 32*i];
    #pragma unroll
    for (int off = 16; off; off >>= 1) s += __shfl_xor_sync(0xffffffff, s, off);
    if (lane == 0) out[row] = s + bias[0];
}

// ---------------------------------------------------------------------------
// Host orchestration
// ---------------------------------------------------------------------------
extern "C" void kernel_launch(void* const* d_in, const int* in_sizes, int n_in,
                              void* d_out, int out_size){
    const float* x      = (const float*)d_in[0];
    const float* m_down = (const float*)d_in[1];
    const float* m_p[2] = {(const float*)d_in[2], (const float*)d_in[3]};
    const float* m_up   = (const float*)d_in[4];
    const float* en_w   = (const float*)d_in[5];
    const float* en_b   = (const float*)d_in[6];
    const float* down_r = (const float*)d_in[7];
    const float* down_w = (const float*)d_in[8];
    const float* pa_r[2]= {(const float*)d_in[9],  (const float*)d_in[17]};
    const float* pa_w[2]= {(const float*)d_in[10], (const float*)d_in[18]};
    const float* f1w[2] = {(const float*)d_in[11], (const float*)d_in[19]};
    const float* f1b[2] = {(const float*)d_in[12], (const float*)d_in[20]};
    const float* f2w[2] = {(const float*)d_in[13], (const float*)d_in[21]};
    const float* f2b[2] = {(const float*)d_in[14], (const float*)d_in[22]};
    const float* rw[2]  = {(const float*)d_in[15], (const float*)d_in[23]};
    const float* rb[2]  = {(const float*)d_in[16], (const float*)d_in[24]};
    const float* up_r   = (const float*)d_in[25];
    const float* up_w   = (const float*)d_in[26];
    const float* de1w   = (const float*)d_in[27];
    const float* de1b   = (const float*)d_in[28];
    const float* de2w   = (const float*)d_in[29];
    const float* de2b   = (const float*)d_in[30];
    float* outp = (float*)d_out;

    __nv_bfloat16 *b0h,*b0l,*lath,*latl,*pah,*pal,*t1h,*t1l,*vh,*vl,*wh,*wl,*phi,*pli;
    float *b1,*t3,*pk;
    cudaGetSymbolAddress((void**)&b0h, g_b0h);  cudaGetSymbolAddress((void**)&b0l, g_b0l);
    cudaGetSymbolAddress((void**)&b1,  g_b1);
    cudaGetSymbolAddress((void**)&lath,g_lath); cudaGetSymbolAddress((void**)&latl,g_latl);
    cudaGetSymbolAddress((void**)&pah, g_pah);  cudaGetSymbolAddress((void**)&pal, g_pal);
    cudaGetSymbolAddress((void**)&t1h, g_t1h);  cudaGetSymbolAddress((void**)&t1l, g_t1l);
    cudaGetSymbolAddress((void**)&t3,  g_t3);
    cudaGetSymbolAddress((void**)&vh,  g_vh);   cudaGetSymbolAddress((void**)&vl,  g_vl);
    cudaGetSymbolAddress((void**)&wh,  g_wh);   cudaGetSymbolAddress((void**)&wl,  g_wl);
    cudaGetSymbolAddress((void**)&phi, g_ph);   cudaGetSymbolAddress((void**)&pli, g_pl);
    cudaGetSymbolAddress((void**)&pk,  g_pk);

    cudaFuncSetAttribute((const void*)wmma_gemm<4>, cudaFuncAttributeMaxDynamicSharedMemorySize, SMEMSZ);
    cudaFuncSetAttribute((const void*)wmma_gemm<5>, cudaFuncAttributeMaxDynamicSharedMemorySize, SMEMSZ);
    cudaFuncSetAttribute((const void*)wmma_gemm<6>, cudaFuncAttributeMaxDynamicSharedMemorySize, SMEMSZ);
    cudaFuncSetAttribute((const void*)wmma_gemm<1>, cudaFuncAttributeMaxDynamicSharedMemorySize, SMEMSZ);
    cudaFuncSetAttribute((const void*)wmma_gemm<0>, cudaFuncAttributeMaxDynamicSharedMemorySize, SMEMSZ);
    cudaFuncSetAttribute((const void*)wmma_gemm<3>, cudaFuncAttributeMaxDynamicSharedMemorySize, SMEMSZ);
    cudaFuncSetAttribute((const void*)wmma_gemm<2>, cudaFuncAttributeMaxDynamicSharedMemorySize, SMEMSZ);

    // 1. encoder -> b0 hi/lo planes
    encoder_kernel<<<MBIG, 256>>>(x, en_w, en_b, b0h, b0l);

    // 2. down pos_att (global): value GEMM, stats+P, split-K apply (4 splits)
    split_attn_w<<<256, 256>>>(down_w, wh, wl);
    wmma_gemm<4><<<dim3(MBIG/128,2,1), 256, SMEMSZ>>>(
        b0h, b0l, 256, 0, wh, wl, 256, nullptr, nullptr, nullptr, vh, vl, NFULL);
    stats_global_f<NFULL><<<HEADS*NLAT, 256>>>(m_down, down_r, phi, pli, NLAT);
    wmma_gemm<6><<<dim3(NLAT/128,2,HEADS*4), 256, SMEMSZ>>>(
        phi, pli, NFULL, NLAT, vh, vl, NFULL, nullptr, nullptr, pk, nullptr, nullptr, 1024);
    apply_reduce<<<HEADS*NLAT*128/256, 256>>>(pk, 4, NLAT, lath, latl, NLAT);

    // 3. latent blocks (local, 30th percentile); split-K 2 applies
    for (int blk = 0; blk < 2; blk++){
        stats_local_f<<<HEADS*NLAT, 256>>>(m_p[blk], pa_r[blk], phi, pli, NLAT);
        split_attn_w<<<256, 256>>>(pa_w[blk], wh, wl);
        wmma_gemm<4><<<dim3(MLAT/128,2,1), 256, SMEMSZ>>>(
            lath, latl, 256, 0, wh, wl, 256, nullptr, nullptr, nullptr, vh, vl, NLAT);
        wmma_gemm<6><<<dim3(NLAT/128,2,HEADS*2), 256, SMEMSZ>>>(
            phi, pli, NLAT, NLAT, vh, vl, NLAT, nullptr, nullptr, pk, nullptr, nullptr, 512);
        apply_reduce<<<HEADS*NLAT*128/256, 256>>>(pk, 2, NLAT, pah, pal, NLAT);
        split_dense_w<<<256, 256>>>(f1w[blk], wh, wl);
        wmma_gemm<1><<<dim3(MLAT/128,2,1), 256, SMEMSZ>>>(
            pah, pal, 256, 0, wh, wl, 256, f1b[blk], nullptr, nullptr, t1h, t1l, 0);
        split_dense_w<<<256, 256>>>(rw[blk], wh, wl);
        wmma_gemm<0><<<dim3(MLAT/128,2,1), 256, SMEMSZ>>>(
            lath, latl, 256, 0, wh, wl, 256, rb[blk], nullptr, t3, nullptr, nullptr, 0);
        split_dense_w<<<256, 256>>>(f2w[blk], wh, wl);
        wmma_gemm<3><<<dim3(MLAT/128,2,1), 256, SMEMSZ>>>(
            t1h, t1l, 256, 0, wh, wl, 256, f2b[blk], t3, nullptr, lath, latl, 0);
    }

    // 4. up pos_att (global): direct apply (plenty of blocks)
    stats_global_f<NLAT><<<HEADS*NFULL, 256>>>(m_up, up_r, phi, pli, NFULL);
    split_attn_w<<<256, 256>>>(up_w, wh, wl);
    wmma_gemm<4><<<dim3(MLAT/128,2,1), 256, SMEMSZ>>>(
        lath, latl, 256, 0, wh, wl, 256, nullptr, nullptr, nullptr, vh, vl, NLAT);
    wmma_gemm<5><<<dim3(NFULL/128,2,HEADS), 256, SMEMSZ>>>(
        phi, pli, NLAT, NFULL, vh, vl, NLAT, nullptr, nullptr, nullptr, b0h, b0l, NFULL);

    // 5. decoder
    split_dense_w<<<256, 256>>>(de1w, wh, wl);
    wmma_gemm<2><<<dim3(MBIG/128,2,1), 256, SMEMSZ>>>(
        b0h, b0l, 256, 0, wh, wl, 256, de1b, nullptr, b1, nullptr, nullptr, 0);
    final_dense_kernel<<<MBIG/8, 256>>>(b1, de2w, de2b, outp);
}